// round 2
// baseline (speedup 1.0000x reference)
#include <cuda_runtime.h>

// Problem constants
// B=4096, N=64, FEAT=128, TIME=128, D_MODEL=256, N_HEAD=2, D_K=128

__device__ float g_M[256 * 512];     // M[k][h*256+c] = sum_d w_qs[k][h*128+d]*w_ks[c][h*128+d]
__device__ float g_P[512 * 256];     // P[(h*256+i)][j] = sum_d w_vs[i][h*128+d]*fc_w[h*128+d][j]
__device__ float g_qk[4096 * 512];   // qk[b][h*256+c]
__device__ float g_kbar[4096 * 512]; // kbar[b][h*256+i]

// ---------------------------------------------------------------------------
// K0: precompute M (256x512) and P (512x256).  33.5M MAC total, trivial.
// ---------------------------------------------------------------------------
__global__ __launch_bounds__(256) void k0_precompute(
    const float* __restrict__ w_qs, const float* __restrict__ w_ks,
    const float* __restrict__ w_vs, const float* __restrict__ fc_w) {
  int o = blockIdx.x * 256 + threadIdx.x;
  if (o < 131072) {
    int k = o >> 9, j = o & 511, h = j >> 8, c = j & 255;
    const float* a = w_qs + k * 256 + h * 128;
    const float* b = w_ks + c * 256 + h * 128;
    float s = 0.f;
#pragma unroll 8
    for (int d = 0; d < 128; d++) s += a[d] * b[d];
    g_M[o] = s;
  } else {
    int o2 = o - 131072;
    int r = o2 >> 8, j = o2 & 255, h = r >> 8, i = r & 255;
    const float* a = w_vs + i * 256 + h * 128;
    float s = 0.f;
#pragma unroll 8
    for (int d = 0; d < 128; d++) s += a[d] * fc_w[(h * 128 + d) * 256 + j];
    g_P[o2] = s;
  }
}

// ---------------------------------------------------------------------------
// K1: qk = Q_in(4096x256) @ M(256x512).  Tiled fp32 GEMM, BM=128 BN=64 BK=16.
// ---------------------------------------------------------------------------
__global__ __launch_bounds__(256) void k1_qk(const float* __restrict__ src,
                                             const float* __restrict__ srct) {
  __shared__ float As[16][132];  // [kk][row], padded
  __shared__ float Bs[16][64];
  int bm = blockIdx.x * 128, bn = blockIdx.y * 64;
  int t = threadIdx.x;
  int ty = t >> 4, tx = t & 15;  // ty: 16 row-groups of 8, tx: 16 col-groups of 4
  float acc[8][4] = {{0.f}};
  for (int k0 = 0; k0 < 256; k0 += 16) {
#pragma unroll
    for (int i = 0; i < 8; i++) {
      int e = t + i * 256;
      int row = e >> 4, kk = e & 15;
      int k = k0 + kk;
      As[kk][row] = (k < 128) ? src[(bm + row) * 128 + k]
                              : srct[(bm + row) * 128 + k - 128];
    }
#pragma unroll
    for (int i = 0; i < 4; i++) {
      int e = t + i * 256;
      int kk = e >> 6, j = e & 63;
      Bs[kk][j] = g_M[(k0 + kk) * 512 + bn + j];
    }
    __syncthreads();
#pragma unroll
    for (int kk = 0; kk < 16; kk++) {
      float a[8], bv[4];
      *(float4*)&a[0] = *(const float4*)&As[kk][ty * 8];
      *(float4*)&a[4] = *(const float4*)&As[kk][ty * 8 + 4];
      *(float4*)&bv[0] = *(const float4*)&Bs[kk][tx * 4];
#pragma unroll
      for (int i = 0; i < 8; i++)
#pragma unroll
        for (int j = 0; j < 4; j++) acc[i][j] += a[i] * bv[j];
    }
    __syncthreads();
  }
#pragma unroll
  for (int i = 0; i < 8; i++) {
    int r = bm + ty * 8 + i;
    float4 v = make_float4(acc[i][0], acc[i][1], acc[i][2], acc[i][3]);
    *(float4*)&g_qk[r * 512 + bn + tx * 4] = v;
  }
}

// ---------------------------------------------------------------------------
// K2: streaming attention. One block per batch. k_in (64x256) in smem,
// logits -> softmax -> attn out + weighted key sum (kbar).
// ---------------------------------------------------------------------------
__global__ __launch_bounds__(256) void k2_attn(const float* __restrict__ seq,
                                               const float* __restrict__ seqt,
                                               const void* __restrict__ maskp,
                                               float* __restrict__ out) {
  extern __shared__ float sm2[];
  float* ks = sm2;             // 64*256 = 16384 floats
  float* qks = ks + 16384;     // 512
  float* lg = qks + 512;       // 128 (2 heads x 64): logits, then attn weights
  float* mb = lg + 128;        // 64 mask flags
  __shared__ int smode;

  int b = blockIdx.x, t = threadIdx.x;

  if (t == 0) {
    // Detect mask storage: int32 (0/1 dwords), float32 (0/1.0f), or byte.
    const unsigned int* mw = (const unsigned int*)maskp;
    int isInt = 1, isFloat = 1;
    for (int i = 0; i < 32; i++) {
      unsigned v = mw[i];
      if (v > 1u) isInt = 0;
      if (v != 0u && v != 0x3F800000u) isFloat = 0;
    }
    smode = isInt ? 0 : (isFloat ? 1 : 2);
  }

  qks[t] = g_qk[b * 512 + t];
  qks[256 + t] = g_qk[b * 512 + 256 + t];

  float4* ks4 = (float4*)ks;
  const float4* s4 = (const float4*)(seq + (long long)b * 8192);
  const float4* st4 = (const float4*)(seqt + (long long)b * 8192);
#pragma unroll
  for (int i = 0; i < 8; i++) {
    int e = t + i * 256;  // 0..2047 float4s
    int n = e >> 5, c4 = e & 31;
    ks4[n * 64 + c4] = s4[e];
    ks4[n * 64 + 32 + c4] = st4[e];
  }
  __syncthreads();

  if (t < 64) {
    int mode = smode;
    int m;
    if (mode == 0)      m = ((const int*)maskp)[b * 64 + t] != 0;
    else if (mode == 1) m = ((const float*)maskp)[b * 64 + t] != 0.f;
    else                m = ((const unsigned char*)maskp)[b * 64 + t] != 0;
    mb[t] = m ? 1.f : 0.f;
  }
  __syncthreads();

  // Logits: warp w handles rows w*8..w*8+7; lane covers 8 dims (4+4 float4).
  int w = t >> 5, l = t & 31;
  float4 qA0 = ((const float4*)qks)[l];
  float4 qB0 = ((const float4*)qks)[32 + l];
  float4 qA1 = ((const float4*)qks)[64 + l];
  float4 qB1 = ((const float4*)qks)[96 + l];
#pragma unroll
  for (int r = 0; r < 8; r++) {
    int n = w * 8 + r;
    float4 kA = ks4[n * 64 + l];
    float4 kB = ks4[n * 64 + 32 + l];
    float s0 = kA.x * qA0.x + kA.y * qA0.y + kA.z * qA0.z + kA.w * qA0.w +
               kB.x * qB0.x + kB.y * qB0.y + kB.z * qB0.z + kB.w * qB0.w;
    float s1 = kA.x * qA1.x + kA.y * qA1.y + kA.z * qA1.z + kA.w * qA1.w +
               kB.x * qB1.x + kB.y * qB1.y + kB.z * qB1.z + kB.w * qB1.w;
#pragma unroll
    for (int o = 16; o; o >>= 1) {
      s0 += __shfl_xor_sync(0xffffffffu, s0, o);
      s1 += __shfl_xor_sync(0xffffffffu, s1, o);
    }
    if (l == 0) {
      const float sc = 0.08838834764831843f;  // 1/sqrt(128)
      int masked = (mb[n] != 0.f);
      lg[n] = masked ? -1e10f : s0 * sc;
      lg[64 + n] = masked ? -1e10f : s1 * sc;
    }
  }
  __syncthreads();

  // Softmax: warp 0 -> head 0, warp 1 -> head 1 (64 values each).
  if (w < 2) {
    float x0 = lg[w * 64 + l], x1 = lg[w * 64 + 32 + l];
    float m = fmaxf(x0, x1);
#pragma unroll
    for (int o = 16; o; o >>= 1) m = fmaxf(m, __shfl_xor_sync(0xffffffffu, m, o));
    float e0 = __expf(x0 - m), e1 = __expf(x1 - m);
    float s = e0 + e1;
#pragma unroll
    for (int o = 16; o; o >>= 1) s += __shfl_xor_sync(0xffffffffu, s, o);
    float inv = 1.f / s;
    float a0 = e0 * inv, a1 = e1 * inv;
    lg[w * 64 + l] = a0;
    lg[w * 64 + 32 + l] = a1;
    // attn_sq output: offset 524288 + (h*4096 + b)*64 + n
    out[524288 + (w * 4096 + b) * 64 + l] = a0;
    out[524288 + (w * 4096 + b) * 64 + 32 + l] = a1;
  }
  __syncthreads();

  // kbar_h[d] = sum_n attn[h][n] * k_in[n][d]
  float kb0 = 0.f, kb1 = 0.f;
#pragma unroll
  for (int n = 0; n < 64; n++) {
    float a0 = lg[n], a1 = lg[64 + n];
    float x = ks[n * 256 + t];
    kb0 += a0 * x;
    kb1 += a1 * x;
  }
  g_kbar[b * 512 + t] = kb0;
  g_kbar[b * 512 + 256 + t] = kb1;
}

// ---------------------------------------------------------------------------
// K3: tail. 32 batches/block. fc_out = kbar@P + fc_b + q_in -> LN ->
// h = relu([ln_out|src] @ fc1_w + fc1_b) -> merged = h @ fc2_w + fc2_b.
// ---------------------------------------------------------------------------
__global__ __launch_bounds__(256) void k3_tail(
    const float* __restrict__ src, const float* __restrict__ srct,
    const float* __restrict__ fc_b, const float* __restrict__ ln_g,
    const float* __restrict__ ln_b, const float* __restrict__ fc1_w,
    const float* __restrict__ fc1_b, const float* __restrict__ fc2_w,
    const float* __restrict__ fc2_b, float* __restrict__ out) {
  extern __shared__ float sm3[];
  float* xh = sm3;           // 32*384
  float* As = xh + 12288;    // 16*36
  float* Bs = As + 576;      // 16*256 (reused as 16*128 later)
  float* hm = Bs + 4096;     // 32*128
  int bb = blockIdx.x * 32;
  int t = threadIdx.x;

  // ---- GEMM1: kbar(32x512) @ P(512x256) ----
  int ty = t >> 6, tx = t & 63;  // 4 row-groups of 8, 64 col-groups of 4
  float acc[8][4] = {{0.f}};
  for (int k0 = 0; k0 < 512; k0 += 16) {
    {
      int e = t;
      int row = e >> 4, kk = e & 15;
      As[kk * 36 + row] = g_kbar[(bb + row) * 512 + k0 + kk];
      e = t + 256;
      row = e >> 4;
      kk = e & 15;
      As[kk * 36 + row] = g_kbar[(bb + row) * 512 + k0 + kk];
    }
#pragma unroll
    for (int i = 0; i < 16; i++) {
      int e = t + i * 256;
      int kk = e >> 8, j = e & 255;
      Bs[kk * 256 + j] = g_P[(k0 + kk) * 256 + j];
    }
    __syncthreads();
#pragma unroll
    for (int kk = 0; kk < 16; kk++) {
      float a[8], bv[4];
      *(float4*)&a[0] = *(const float4*)&As[kk * 36 + ty * 8];
      *(float4*)&a[4] = *(const float4*)&As[kk * 36 + ty * 8 + 4];
      *(float4*)&bv[0] = *(const float4*)&Bs[kk * 256 + tx * 4];
#pragma unroll
      for (int i = 0; i < 8; i++)
#pragma unroll
        for (int j = 0; j < 4; j++) acc[i][j] += a[i] * bv[j];
    }
    __syncthreads();
  }
  // epilogue: + fc_b + residual q_in, into xh cols 0..255
#pragma unroll
  for (int i = 0; i < 8; i++) {
    int r = ty * 8 + i;
    int gb = bb + r;
#pragma unroll
    for (int j = 0; j < 4; j++) {
      int c = tx * 4 + j;
      float resid = (c < 128) ? src[gb * 128 + c] : srct[gb * 128 + c - 128];
      xh[r * 384 + c] = acc[i][j] + fc_b[c] + resid;
    }
  }
  // src into xh cols 256..383
#pragma unroll
  for (int i = 0; i < 16; i++) {
    int e = t + i * 256;
    int r = e >> 7, c = e & 127;
    xh[r * 384 + 256 + c] = src[(bb + r) * 128 + c];
  }
  __syncthreads();

  // ---- LayerNorm over cols 0..255, in place ----
  int w = t >> 5, l = t & 31;
#pragma unroll
  for (int rr = 0; rr < 4; rr++) {
    int r = w * 4 + rr;
    float s1 = 0.f, s2 = 0.f;
#pragma unroll
    for (int q = 0; q < 8; q++) {
      float x = xh[r * 384 + l + 32 * q];
      s1 += x;
      s2 += x * x;
    }
#pragma unroll
    for (int o = 16; o; o >>= 1) {
      s1 += __shfl_xor_sync(0xffffffffu, s1, o);
      s2 += __shfl_xor_sync(0xffffffffu, s2, o);
    }
    float mu = s1 * (1.f / 256.f);
    float var = s2 * (1.f / 256.f) - mu * mu;
    float rs = rsqrtf(var + 1e-5f);
#pragma unroll
    for (int q = 0; q < 8; q++) {
      int c = l + 32 * q;
      float x = xh[r * 384 + c];
      xh[r * 384 + c] = (x - mu) * rs * ln_g[c] + ln_b[c];
    }
  }
  __syncthreads();

  // ---- GEMM2: xh(32x384) @ fc1_w(384x128), relu -> hm ----
  int ty2 = t >> 5, tx2 = t & 31;  // 8 row-groups of 4, 32 col-groups of 4
  float a2[4][4] = {{0.f}};
  for (int k0 = 0; k0 < 384; k0 += 16) {
#pragma unroll
    for (int i = 0; i < 8; i++) {
      int e = t + i * 256;
      int kk = e >> 7, j = e & 127;
      Bs[kk * 128 + j] = fc1_w[(k0 + kk) * 128 + j];
    }
    __syncthreads();
#pragma unroll
    for (int kk = 0; kk < 16; kk++) {
      float av[4], bv[4];
#pragma unroll
      for (int i = 0; i < 4; i++) av[i] = xh[(ty2 * 4 + i) * 384 + k0 + kk];
      *(float4*)&bv[0] = *(const float4*)&Bs[kk * 128 + tx2 * 4];
#pragma unroll
      for (int i = 0; i < 4; i++)
#pragma unroll
        for (int j = 0; j < 4; j++) a2[i][j] += av[i] * bv[j];
    }
    __syncthreads();
  }
#pragma unroll
  for (int i = 0; i < 4; i++)
#pragma unroll
    for (int j = 0; j < 4; j++) {
      int r = ty2 * 4 + i, c = tx2 * 4 + j;
      hm[r * 128 + c] = fmaxf(a2[i][j] + fc1_b[c], 0.f);
    }
  __syncthreads();

  // ---- GEMM3: hm(32x128) @ fc2_w(128x128) ----
  float a3[4][4] = {{0.f}};
  for (int k0 = 0; k0 < 128; k0 += 16) {
#pragma unroll
    for (int i = 0; i < 8; i++) {
      int e = t + i * 256;
      int kk = e >> 7, j = e & 127;
      Bs[kk * 128 + j] = fc2_w[(k0 + kk) * 128 + j];
    }
    __syncthreads();
#pragma unroll
    for (int kk = 0; kk < 16; kk++) {
      float av[4], bv[4];
#pragma unroll
      for (int i = 0; i < 4; i++) av[i] = hm[(ty2 * 4 + i) * 128 + k0 + kk];
      *(float4*)&bv[0] = *(const float4*)&Bs[kk * 128 + tx2 * 4];
#pragma unroll
      for (int i = 0; i < 4; i++)
#pragma unroll
        for (int j = 0; j < 4; j++) a3[i][j] += av[i] * bv[j];
    }
    __syncthreads();
  }
#pragma unroll
  for (int i = 0; i < 4; i++)
#pragma unroll
    for (int j = 0; j < 4; j++) {
      int r = bb + ty2 * 4 + i, c = tx2 * 4 + j;
      out[r * 128 + c] = a3[i][j] + fc2_b[c];
    }
}

// ---------------------------------------------------------------------------
extern "C" void kernel_launch(void* const* d_in, const int* in_sizes, int n_in,
                              void* d_out, int out_size) {
  const float* src   = (const float*)d_in[0];
  const float* src_t = (const float*)d_in[1];
  const float* seq   = (const float*)d_in[2];
  const float* seq_t = (const float*)d_in[3];
  const void*  mask  = d_in[4];
  const float* w_qs  = (const float*)d_in[5];
  const float* w_ks  = (const float*)d_in[6];
  const float* w_vs  = (const float*)d_in[7];
  const float* fc_w  = (const float*)d_in[8];
  const float* fc_b  = (const float*)d_in[9];
  const float* ln_g  = (const float*)d_in[10];
  const float* ln_b  = (const float*)d_in[11];
  const float* fc1_w = (const float*)d_in[12];
  const float* fc1_b = (const float*)d_in[13];
  const float* fc2_w = (const float*)d_in[14];
  const float* fc2_b = (const float*)d_in[15];
  float* out = (float*)d_out;

  const int K2_SMEM = (16384 + 512 + 128 + 64) * 4;          // 68352 B
  const int K3_SMEM = (12288 + 576 + 4096 + 4096) * 4;       // 84224 B
  cudaFuncSetAttribute(k2_attn, cudaFuncAttributeMaxDynamicSharedMemorySize, K2_SMEM);
  cudaFuncSetAttribute(k3_tail, cudaFuncAttributeMaxDynamicSharedMemorySize, K3_SMEM);

  k0_precompute<<<1024, 256>>>(w_qs, w_ks, w_vs, fc_w);
  k1_qk<<<dim3(32, 8), 256>>>(src, src_t);
  k2_attn<<<4096, 256, K2_SMEM>>>(seq, seq_t, mask, out);
  k3_tail<<<128, 256, K3_SMEM>>>(src, src_t, fc_b, ln_g, ln_b, fc1_w, fc1_b,
                                 fc2_w, fc2_b, out);
}

// round 3
// speedup vs baseline: 1.0292x; 1.0292x over previous
#include <cuda_runtime.h>

// B=4096, N=64, FEAT=128, TIME=128, D_MODEL=256, N_HEAD=2, D_K=128
typedef unsigned long long ull;

__device__ float g_M[256 * 512];     // M[k][h*256+c]
__device__ float g_P[512 * 256];     // P[(h*256+i)][j]
__device__ float g_qk[4096 * 512];   // qk[b][h*256+c]
__device__ float g_kbar[4096 * 512]; // kbar[b][h*256+i]
__device__ float g_x[4096 * 256];    // fc_out + q_in residual (pre-LN)

__device__ __forceinline__ ull pk2(float x) {
  ull r; asm("mov.b64 %0,{%1,%1};" : "=l"(r) : "f"(x)); return r;
}
__device__ __forceinline__ void fma2(ull& d, ull a, ull b) {
  asm("fma.rn.f32x2 %0,%1,%2,%0;" : "+l"(d) : "l"(a), "l"(b));
}
__device__ __forceinline__ float2 upk(ull v) {
  float2 f; asm("mov.b64 {%0,%1},%2;" : "=f"(f.x), "=f"(f.y) : "l"(v)); return f;
}

// ---------------------------------------------------------------------------
// K0: precompute M (256x512) and P (512x256).
// ---------------------------------------------------------------------------
__global__ __launch_bounds__(256) void k0_precompute(
    const float* __restrict__ w_qs, const float* __restrict__ w_ks,
    const float* __restrict__ w_vs, const float* __restrict__ fc_w) {
  int o = blockIdx.x * 256 + threadIdx.x;
  if (o < 131072) {
    int k = o >> 9, j = o & 511, h = j >> 8, c = j & 255;
    const float* a = w_qs + k * 256 + h * 128;
    const float* b = w_ks + c * 256 + h * 128;
    float s = 0.f;
#pragma unroll 8
    for (int d = 0; d < 128; d++) s += a[d] * b[d];
    g_M[o] = s;
  } else {
    int o2 = o - 131072;
    int r = o2 >> 8, j = o2 & 255, h = r >> 8, i = r & 255;
    const float* a = w_vs + i * 256 + h * 128;
    float s = 0.f;
#pragma unroll 8
    for (int d = 0; d < 128; d++) s += a[d] * fc_w[(h * 128 + d) * 256 + j];
    g_P[o2] = s;
  }
}

// ---------------------------------------------------------------------------
// K1: qk = Q_in(4096x256) @ M(256x512). BM=128 BN=128 BK=16, 8x8/thread,
// f32x2 FMA, register-prefetch pipeline. grid (32,4).
// ---------------------------------------------------------------------------
__global__ __launch_bounds__(256) void k1_qk(const float* __restrict__ src,
                                             const float* __restrict__ srct) {
  __shared__ float As[16][128];  // [kk][row]
  __shared__ float Bs[16][128];  // [kk][col]
  int bm = blockIdx.x * 128, bn = blockIdx.y * 128;
  int t = threadIdx.x;
  int ty = t >> 4, tx = t & 15;  // 8 rows x 8 cols per thread
  ull acc[8][4];
#pragma unroll
  for (int i = 0; i < 8; i++)
#pragma unroll
    for (int j = 0; j < 4; j++) acc[i][j] = 0ull;

  float4 pa[2], pb[2];
  auto loadA = [&](int kt) {
#pragma unroll
    for (int i = 0; i < 2; i++) {
      int e = t + i * 256, r = e >> 2, g = e & 3, k = kt * 16 + g * 4;
      pa[i] = (k < 128) ? *(const float4*)&src[(bm + r) * 128 + k]
                        : *(const float4*)&srct[(bm + r) * 128 + k - 128];
    }
  };
  auto loadB = [&](int kt) {
#pragma unroll
    for (int i = 0; i < 2; i++) {
      int e = t + i * 256, kk = e >> 5, n4 = e & 31;
      pb[i] = *(const float4*)&g_M[(kt * 16 + kk) * 512 + bn + n4 * 4];
    }
  };
  loadA(0); loadB(0);
  for (int kt = 0; kt < 16; kt++) {
#pragma unroll
    for (int i = 0; i < 2; i++) {
      int e = t + i * 256, r = e >> 2, g = e & 3;
      As[g * 4 + 0][r] = pa[i].x; As[g * 4 + 1][r] = pa[i].y;
      As[g * 4 + 2][r] = pa[i].z; As[g * 4 + 3][r] = pa[i].w;
    }
#pragma unroll
    for (int i = 0; i < 2; i++) {
      int e = t + i * 256, kk = e >> 5, n4 = e & 31;
      *(float4*)&Bs[kk][n4 * 4] = pb[i];
    }
    __syncthreads();
    if (kt < 15) { loadA(kt + 1); loadB(kt + 1); }
#pragma unroll
    for (int kk = 0; kk < 16; kk++) {
      float4 a0 = *(const float4*)&As[kk][ty * 8];
      float4 a1 = *(const float4*)&As[kk][ty * 8 + 4];
      ull A[8] = {pk2(a0.x), pk2(a0.y), pk2(a0.z), pk2(a0.w),
                  pk2(a1.x), pk2(a1.y), pk2(a1.z), pk2(a1.w)};
      ull b[4];
#pragma unroll
      for (int j = 0; j < 4; j++) b[j] = *(const ull*)&Bs[kk][tx * 8 + 2 * j];
#pragma unroll
      for (int i = 0; i < 8; i++)
#pragma unroll
        for (int j = 0; j < 4; j++) fma2(acc[i][j], A[i], b[j]);
    }
    __syncthreads();
  }
#pragma unroll
  for (int i = 0; i < 8; i++) {
    int r = bm + ty * 8 + i;
    float2 p0 = upk(acc[i][0]), p1 = upk(acc[i][1]);
    float2 p2 = upk(acc[i][2]), p3 = upk(acc[i][3]);
    *(float4*)&g_qk[r * 512 + bn + tx * 8] = make_float4(p0.x, p0.y, p1.x, p1.y);
    *(float4*)&g_qk[r * 512 + bn + tx * 8 + 4] = make_float4(p2.x, p2.y, p3.x, p3.y);
  }
}

// ---------------------------------------------------------------------------
// K2: streaming attention. One block per batch. Logits computed DURING the
// global->smem load (warp w owns keys w, w+8, ..., w+56), then softmax,
// then kbar from smem.
// ---------------------------------------------------------------------------
__global__ __launch_bounds__(256) void k2_attn(const float* __restrict__ seq,
                                               const float* __restrict__ seqt,
                                               const void* __restrict__ maskp,
                                               float* __restrict__ out) {
  extern __shared__ float sm2[];
  float* ks = sm2;           // 64*256 = 16384 floats
  float* lg = ks + 16384;    // 128: logits then attn weights
  __shared__ int smode;

  int b = blockIdx.x, t = threadIdx.x;
  int w = t >> 5, l = t & 31;

  if (t == 0) {
    const unsigned int* mw = (const unsigned int*)maskp;
    int isInt = 1, isFloat = 1;
    for (int i = 0; i < 32; i++) {
      unsigned v = mw[i];
      if (v > 1u) isInt = 0;
      if (v != 0u && v != 0x3F800000u) isFloat = 0;
    }
    smode = isInt ? 0 : (isFloat ? 1 : 2);
  }

  const float4* qv = (const float4*)(g_qk + b * 512);
  float4 qA0 = qv[l], qB0 = qv[32 + l], qA1 = qv[64 + l], qB1 = qv[96 + l];

  float4* ks4 = (float4*)ks;
  const float4* s4 = (const float4*)(seq + (long long)b * 8192);
  const float4* st4 = (const float4*)(seqt + (long long)b * 8192);
  const float sc = 0.08838834764831843f;  // 1/sqrt(128)
#pragma unroll
  for (int i = 0; i < 8; i++) {
    int e = t + i * 256;
    int n = w + 8 * i;  // e>>5 == w + 8*i, e&31 == l
    float4 kA = s4[e], kB = st4[e];
    ks4[n * 64 + l] = kA;
    ks4[n * 64 + 32 + l] = kB;
    float s0 = kA.x * qA0.x + kA.y * qA0.y + kA.z * qA0.z + kA.w * qA0.w +
               kB.x * qB0.x + kB.y * qB0.y + kB.z * qB0.z + kB.w * qB0.w;
    float s1 = kA.x * qA1.x + kA.y * qA1.y + kA.z * qA1.z + kA.w * qA1.w +
               kB.x * qB1.x + kB.y * qB1.y + kB.z * qB1.z + kB.w * qB1.w;
#pragma unroll
    for (int o = 16; o; o >>= 1) {
      s0 += __shfl_xor_sync(0xffffffffu, s0, o);
      s1 += __shfl_xor_sync(0xffffffffu, s1, o);
    }
    if (l == 0) { lg[n] = s0 * sc; lg[64 + n] = s1 * sc; }
  }
  __syncthreads();

  // Softmax: warp 0 -> head 0, warp 1 -> head 1.
  if (w < 2) {
    int mode = smode;
    int i0 = b * 64 + l, i1 = i0 + 32, m0, m1;
    if (mode == 0) {
      m0 = ((const int*)maskp)[i0] != 0; m1 = ((const int*)maskp)[i1] != 0;
    } else if (mode == 1) {
      m0 = ((const float*)maskp)[i0] != 0.f; m1 = ((const float*)maskp)[i1] != 0.f;
    } else {
      m0 = ((const unsigned char*)maskp)[i0] != 0; m1 = ((const unsigned char*)maskp)[i1] != 0;
    }
    float x0 = m0 ? -1e10f : lg[w * 64 + l];
    float x1 = m1 ? -1e10f : lg[w * 64 + 32 + l];
    float m = fmaxf(x0, x1);
#pragma unroll
    for (int o = 16; o; o >>= 1) m = fmaxf(m, __shfl_xor_sync(0xffffffffu, m, o));
    float e0 = __expf(x0 - m), e1 = __expf(x1 - m);
    float s = e0 + e1;
#pragma unroll
    for (int o = 16; o; o >>= 1) s += __shfl_xor_sync(0xffffffffu, s, o);
    float inv = 1.f / s;
    float a0 = e0 * inv, a1 = e1 * inv;
    lg[w * 64 + l] = a0;
    lg[w * 64 + 32 + l] = a1;
    out[524288 + (w * 4096 + b) * 64 + l] = a0;
    out[524288 + (w * 4096 + b) * 64 + 32 + l] = a1;
  }
  __syncthreads();

  // kbar_h[d] = sum_n attn[h][n] * k_in[n][d]
  float kb0 = 0.f, kb1 = 0.f;
#pragma unroll
  for (int n = 0; n < 64; n++) {
    float a0 = lg[n], a1 = lg[64 + n];
    float x = ks[n * 256 + t];
    kb0 += a0 * x;
    kb1 += a1 * x;
  }
  g_kbar[b * 512 + t] = kb0;
  g_kbar[b * 512 + 256 + t] = kb1;
}

// ---------------------------------------------------------------------------
// K3a: g_x = kbar(4096x512) @ P(512x256) + fc_b + q_in. BM=128 BN=64 BK=16,
// 8x4/thread, f32x2, prefetch pipeline. grid (32,4).
// ---------------------------------------------------------------------------
__global__ __launch_bounds__(256) void k3a_fc(const float* __restrict__ src,
                                              const float* __restrict__ srct,
                                              const float* __restrict__ fc_b) {
  __shared__ float As[16][128];
  __shared__ float Bs[16][64];
  int bm = blockIdx.x * 128, bn = blockIdx.y * 64;
  int t = threadIdx.x;
  int ty = t >> 4, tx = t & 15;  // 8 rows x 4 cols
  ull acc[8][2];
#pragma unroll
  for (int i = 0; i < 8; i++) { acc[i][0] = 0ull; acc[i][1] = 0ull; }

  float4 pa[2], pb;
  auto loadA = [&](int kt) {
#pragma unroll
    for (int i = 0; i < 2; i++) {
      int e = t + i * 256, r = e >> 2, g = e & 3;
      pa[i] = *(const float4*)&g_kbar[(bm + r) * 512 + kt * 16 + g * 4];
    }
  };
  auto loadB = [&](int kt) {
    int kk = t >> 4, n4 = t & 15;
    pb = *(const float4*)&g_P[(kt * 16 + kk) * 256 + bn + n4 * 4];
  };
  loadA(0); loadB(0);
  for (int kt = 0; kt < 32; kt++) {
#pragma unroll
    for (int i = 0; i < 2; i++) {
      int e = t + i * 256, r = e >> 2, g = e & 3;
      As[g * 4 + 0][r] = pa[i].x; As[g * 4 + 1][r] = pa[i].y;
      As[g * 4 + 2][r] = pa[i].z; As[g * 4 + 3][r] = pa[i].w;
    }
    { int kk = t >> 4, n4 = t & 15; *(float4*)&Bs[kk][n4 * 4] = pb; }
    __syncthreads();
    if (kt < 31) { loadA(kt + 1); loadB(kt + 1); }
#pragma unroll
    for (int kk = 0; kk < 16; kk++) {
      float4 a0 = *(const float4*)&As[kk][ty * 8];
      float4 a1 = *(const float4*)&As[kk][ty * 8 + 4];
      ull A[8] = {pk2(a0.x), pk2(a0.y), pk2(a0.z), pk2(a0.w),
                  pk2(a1.x), pk2(a1.y), pk2(a1.z), pk2(a1.w)};
      ull b0 = *(const ull*)&Bs[kk][tx * 4];
      ull b1 = *(const ull*)&Bs[kk][tx * 4 + 2];
#pragma unroll
      for (int i = 0; i < 8; i++) { fma2(acc[i][0], A[i], b0); fma2(acc[i][1], A[i], b1); }
    }
    __syncthreads();
  }
#pragma unroll
  for (int i = 0; i < 8; i++) {
    int r = bm + ty * 8 + i;
    float2 p0 = upk(acc[i][0]), p1 = upk(acc[i][1]);
    float o[4] = {p0.x, p0.y, p1.x, p1.y};
    float4 v;
    float* vp = &v.x;
#pragma unroll
    for (int j = 0; j < 4; j++) {
      int c = bn + tx * 4 + j;
      float resid = (c < 128) ? src[r * 128 + c] : srct[r * 128 + c - 128];
      vp[j] = o[j] + fc_b[c] + resid;
    }
    *(float4*)&g_x[r * 256 + bn + tx * 4] = v;
  }
}

// ---------------------------------------------------------------------------
// K3b: per 32-batch tile: LN(g_x) -> xh[:,0:256], src -> xh[:,256:384],
// GEMM2 relu, GEMM3 -> out. f32x2 + prefetch. grid 128.
// ---------------------------------------------------------------------------
__global__ __launch_bounds__(256) void k3b_ffn(
    const float* __restrict__ src, const float* __restrict__ ln_g,
    const float* __restrict__ ln_b, const float* __restrict__ fc1_w,
    const float* __restrict__ fc1_b, const float* __restrict__ fc2_w,
    const float* __restrict__ fc2_b, float* __restrict__ out) {
  extern __shared__ float sm3[];
  float* xh = sm3;           // 32 x 388 (padded)
  float* Bs = xh + 32 * 388; // 16 x 128
  float* hm = Bs + 2048;     // 32 x 132 (padded)
  int bb = blockIdx.x * 32;
  int t = threadIdx.x;
  int w = t >> 5, l = t & 31;

  // load g_x tile (32x256) and src (32x128)
#pragma unroll
  for (int i = 0; i < 8; i++) {
    int e = t + i * 256, r = e >> 6, c4 = e & 63;
    *(float4*)&xh[r * 388 + c4 * 4] = *(const float4*)&g_x[(bb + r) * 256 + c4 * 4];
  }
#pragma unroll
  for (int i = 0; i < 4; i++) {
    int e = t + i * 256, r = e >> 5, c4 = e & 31;
    *(float4*)&xh[r * 388 + 256 + c4 * 4] = *(const float4*)&src[(bb + r) * 128 + c4 * 4];
  }
  __syncthreads();

  // LayerNorm over cols 0..255 in place (warp w: rows w*4..w*4+3)
#pragma unroll
  for (int rr = 0; rr < 4; rr++) {
    int r = w * 4 + rr;
    float s1 = 0.f, s2 = 0.f;
#pragma unroll
    for (int q = 0; q < 8; q++) {
      float x = xh[r * 388 + l + 32 * q];
      s1 += x; s2 += x * x;
    }
#pragma unroll
    for (int o = 16; o; o >>= 1) {
      s1 += __shfl_xor_sync(0xffffffffu, s1, o);
      s2 += __shfl_xor_sync(0xffffffffu, s2, o);
    }
    float mu = s1 * (1.f / 256.f);
    float var = s2 * (1.f / 256.f) - mu * mu;
    float rs = rsqrtf(var + 1e-5f);
#pragma unroll
    for (int q = 0; q < 8; q++) {
      int c = l + 32 * q;
      float x = xh[r * 388 + c];
      xh[r * 388 + c] = (x - mu) * rs * ln_g[c] + ln_b[c];
    }
  }
  __syncthreads();

  int ty2 = w, tx2 = l;  // rows ty2*4.., cols tx2*4..
  // ---- GEMM2: xh(32x384) @ fc1_w(384x128) + relu -> hm ----
  {
    ull acc[4][2];
#pragma unroll
    for (int i = 0; i < 4; i++) { acc[i][0] = 0ull; acc[i][1] = 0ull; }
    float4 pb[2];
    auto loadB = [&](int kt) {
#pragma unroll
      for (int i = 0; i < 2; i++) {
        int e = t + i * 256, kk = e >> 5, c4 = e & 31;
        pb[i] = *(const float4*)&fc1_w[(kt * 16 + kk) * 128 + c4 * 4];
      }
    };
    loadB(0);
    for (int kt = 0; kt < 24; kt++) {
#pragma unroll
      for (int i = 0; i < 2; i++) {
        int e = t + i * 256, kk = e >> 5, c4 = e & 31;
        *(float4*)&Bs[kk * 128 + c4 * 4] = pb[i];
      }
      __syncthreads();
      if (kt < 23) loadB(kt + 1);
#pragma unroll
      for (int kk = 0; kk < 16; kk++) {
        int k = kt * 16 + kk;
        ull A[4];
#pragma unroll
        for (int i = 0; i < 4; i++) A[i] = pk2(xh[(ty2 * 4 + i) * 388 + k]);
        ull b0 = *(const ull*)&Bs[kk * 128 + tx2 * 4];
        ull b1 = *(const ull*)&Bs[kk * 128 + tx2 * 4 + 2];
#pragma unroll
        for (int i = 0; i < 4; i++) { fma2(acc[i][0], A[i], b0); fma2(acc[i][1], A[i], b1); }
      }
      __syncthreads();
    }
#pragma unroll
    for (int i = 0; i < 4; i++) {
      float2 p0 = upk(acc[i][0]), p1 = upk(acc[i][1]);
      int r = ty2 * 4 + i, c = tx2 * 4;
      hm[r * 132 + c + 0] = fmaxf(p0.x + fc1_b[c + 0], 0.f);
      hm[r * 132 + c + 1] = fmaxf(p0.y + fc1_b[c + 1], 0.f);
      hm[r * 132 + c + 2] = fmaxf(p1.x + fc1_b[c + 2], 0.f);
      hm[r * 132 + c + 3] = fmaxf(p1.y + fc1_b[c + 3], 0.f);
    }
  }
  __syncthreads();

  // ---- GEMM3: hm(32x128) @ fc2_w(128x128) -> out ----
  {
    ull acc[4][2];
#pragma unroll
    for (int i = 0; i < 4; i++) { acc[i][0] = 0ull; acc[i][1] = 0ull; }
    float4 pb[2];
    auto loadB = [&](int kt) {
#pragma unroll
      for (int i = 0; i < 2; i++) {
        int e = t + i * 256, kk = e >> 5, c4 = e & 31;
        pb[i] = *(const float4*)&fc2_w[(kt * 16 + kk) * 128 + c4 * 4];
      }
    };
    loadB(0);
    for (int kt = 0; kt < 8; kt++) {
#pragma unroll
      for (int i = 0; i < 2; i++) {
        int e = t + i * 256, kk = e >> 5, c4 = e & 31;
        *(float4*)&Bs[kk * 128 + c4 * 4] = pb[i];
      }
      __syncthreads();
      if (kt < 7) loadB(kt + 1);
#pragma unroll
      for (int kk = 0; kk < 16; kk++) {
        int k = kt * 16 + kk;
        ull A[4];
#pragma unroll
        for (int i = 0; i < 4; i++) A[i] = pk2(hm[(ty2 * 4 + i) * 132 + k]);
        ull b0 = *(const ull*)&Bs[kk * 128 + tx2 * 4];
        ull b1 = *(const ull*)&Bs[kk * 128 + tx2 * 4 + 2];
#pragma unroll
        for (int i = 0; i < 4; i++) { fma2(acc[i][0], A[i], b0); fma2(acc[i][1], A[i], b1); }
      }
      __syncthreads();
    }
#pragma unroll
    for (int i = 0; i < 4; i++) {
      float2 p0 = upk(acc[i][0]), p1 = upk(acc[i][1]);
      int r = bb + ty2 * 4 + i, c = tx2 * 4;
      float4 v = make_float4(p0.x + fc2_b[c], p0.y + fc2_b[c + 1],
                             p1.x + fc2_b[c + 2], p1.y + fc2_b[c + 3]);
      *(float4*)&out[r * 128 + c] = v;
    }
  }
}

// ---------------------------------------------------------------------------
extern "C" void kernel_launch(void* const* d_in, const int* in_sizes, int n_in,
                              void* d_out, int out_size) {
  const float* src   = (const float*)d_in[0];
  const float* src_t = (const float*)d_in[1];
  const float* seq   = (const float*)d_in[2];
  const float* seq_t = (const float*)d_in[3];
  const void*  mask  = d_in[4];
  const float* w_qs  = (const float*)d_in[5];
  const float* w_ks  = (const float*)d_in[6];
  const float* w_vs  = (const float*)d_in[7];
  const float* fc_w  = (const float*)d_in[8];
  const float* fc_b  = (const float*)d_in[9];
  const float* ln_g  = (const float*)d_in[10];
  const float* ln_b  = (const float*)d_in[11];
  const float* fc1_w = (const float*)d_in[12];
  const float* fc1_b = (const float*)d_in[13];
  const float* fc2_w = (const float*)d_in[14];
  const float* fc2_b = (const float*)d_in[15];
  float* out = (float*)d_out;

  const int K2_SMEM = (16384 + 128) * 4;                 // 66048 B
  const int K3B_SMEM = (32 * 388 + 2048 + 32 * 132) * 4; // 74752 B
  cudaFuncSetAttribute(k2_attn, cudaFuncAttributeMaxDynamicSharedMemorySize, K2_SMEM);
  cudaFuncSetAttribute(k3b_ffn, cudaFuncAttributeMaxDynamicSharedMemorySize, K3B_SMEM);

  k0_precompute<<<1024, 256>>>(w_qs, w_ks, w_vs, fc_w);
  k1_qk<<<dim3(32, 4), 256>>>(src, src_t);
  k2_attn<<<4096, 256, K2_SMEM>>>(seq, seq_t, mask, out);
  k3a_fc<<<dim3(32, 4), 256>>>(src, src_t, fc_b);
  k3b_ffn<<<128, 256, K3B_SMEM>>>(src, ln_g, ln_b, fc1_w, fc1_b, fc2_w, fc2_b,
                                  out);
}

// round 4
// speedup vs baseline: 1.0760x; 1.0455x over previous
#include <cuda_runtime.h>

// B=4096, N=64, FEAT=128, TIME=128, D_MODEL=256, N_HEAD=2, D_K=128
typedef unsigned long long ull;

__device__ float g_M[256 * 512];     // M[k][h*256+c]
__device__ float g_P[512 * 256];     // P[(h*256+i)][j]
__device__ float g_qk[4096 * 512];   // qk[b][h*256+c]
__device__ float g_kbar[4096 * 512]; // kbar[b][h*256+i]
__device__ float g_x[4096 * 256];    // fc_out + q_in residual (pre-LN)

__device__ __forceinline__ ull pk2(float x) {
  ull r; asm("mov.b64 %0,{%1,%1};" : "=l"(r) : "f"(x)); return r;
}
__device__ __forceinline__ void fma2(ull& d, ull a, ull b) {
  asm("fma.rn.f32x2 %0,%1,%2,%0;" : "+l"(d) : "l"(a), "l"(b));
}
__device__ __forceinline__ float2 upk(ull v) {
  float2 f; asm("mov.b64 {%0,%1},%2;" : "=f"(f.x), "=f"(f.y) : "l"(v)); return f;
}

// ---------------------------------------------------------------------------
// K0: precompute M (256x512) and P (512x256).
// ---------------------------------------------------------------------------
__global__ __launch_bounds__(256) void k0_precompute(
    const float* __restrict__ w_qs, const float* __restrict__ w_ks,
    const float* __restrict__ w_vs, const float* __restrict__ fc_w) {
  int o = blockIdx.x * 256 + threadIdx.x;
  if (o < 131072) {
    int k = o >> 9, j = o & 511, h = j >> 8, c = j & 255;
    const float* a = w_qs + k * 256 + h * 128;
    const float* b = w_ks + c * 256 + h * 128;
    float s = 0.f;
#pragma unroll 8
    for (int d = 0; d < 128; d++) s += a[d] * b[d];
    g_M[o] = s;
  } else {
    int o2 = o - 131072;
    int r = o2 >> 8, j = o2 & 255, h = r >> 8, i = r & 255;
    const float* a = w_vs + i * 256 + h * 128;
    float s = 0.f;
#pragma unroll 8
    for (int d = 0; d < 128; d++) s += a[d] * fc_w[(h * 128 + d) * 256 + j];
    g_P[o2] = s;
  }
}

// ---------------------------------------------------------------------------
// K1: qk = Q_in(4096x256) @ M(256x512). BM=64 BN=128 BK=16, 4x8/thread,
// f32x2 + prefetch. grid (64,4)=256.
// ---------------------------------------------------------------------------
__global__ __launch_bounds__(256) void k1_qk(const float* __restrict__ src,
                                             const float* __restrict__ srct) {
  __shared__ float As[16][64];
  __shared__ float Bs[16][128];
  int bm = blockIdx.x * 64, bn = blockIdx.y * 128;
  int t = threadIdx.x;
  int ty = t >> 4, tx = t & 15;  // 16 row-groups of 4, 16 col-groups of 8
  ull acc[4][4];
#pragma unroll
  for (int i = 0; i < 4; i++)
#pragma unroll
    for (int j = 0; j < 4; j++) acc[i][j] = 0ull;

  float4 pa, pb[2];
  auto loadA = [&](int kt) {
    int r = t >> 2, g = t & 3, k = kt * 16 + g * 4;
    pa = (k < 128) ? *(const float4*)&src[(bm + r) * 128 + k]
                   : *(const float4*)&srct[(bm + r) * 128 + k - 128];
  };
  auto loadB = [&](int kt) {
#pragma unroll
    for (int i = 0; i < 2; i++) {
      int e = t + i * 256, kk = e >> 5, n4 = e & 31;
      pb[i] = *(const float4*)&g_M[(kt * 16 + kk) * 512 + bn + n4 * 4];
    }
  };
  loadA(0); loadB(0);
  for (int kt = 0; kt < 16; kt++) {
    {
      int r = t >> 2, g = t & 3;
      As[g * 4 + 0][r] = pa.x; As[g * 4 + 1][r] = pa.y;
      As[g * 4 + 2][r] = pa.z; As[g * 4 + 3][r] = pa.w;
    }
#pragma unroll
    for (int i = 0; i < 2; i++) {
      int e = t + i * 256, kk = e >> 5, n4 = e & 31;
      *(float4*)&Bs[kk][n4 * 4] = pb[i];
    }
    __syncthreads();
    if (kt < 15) { loadA(kt + 1); loadB(kt + 1); }
#pragma unroll
    for (int kk = 0; kk < 16; kk++) {
      float4 a0 = *(const float4*)&As[kk][ty * 4];
      ull A[4] = {pk2(a0.x), pk2(a0.y), pk2(a0.z), pk2(a0.w)};
      ull b[4];
#pragma unroll
      for (int j = 0; j < 4; j++) b[j] = *(const ull*)&Bs[kk][tx * 8 + 2 * j];
#pragma unroll
      for (int i = 0; i < 4; i++)
#pragma unroll
        for (int j = 0; j < 4; j++) fma2(acc[i][j], A[i], b[j]);
    }
    __syncthreads();
  }
#pragma unroll
  for (int i = 0; i < 4; i++) {
    int r = bm + ty * 4 + i;
    float2 p0 = upk(acc[i][0]), p1 = upk(acc[i][1]);
    float2 p2 = upk(acc[i][2]), p3 = upk(acc[i][3]);
    *(float4*)&g_qk[r * 512 + bn + tx * 8] = make_float4(p0.x, p0.y, p1.x, p1.y);
    *(float4*)&g_qk[r * 512 + bn + tx * 8 + 4] = make_float4(p2.x, p2.y, p3.x, p3.y);
  }
}

// ---------------------------------------------------------------------------
// K2: online-softmax streaming attention. One block per batch, NO key smem.
// Warp w owns keys w, w+8, ..., w+56 with running (max, sum, acc) registers.
// 8-warp combine via smem.
// ---------------------------------------------------------------------------
__global__ __launch_bounds__(256) void k2_attn(const float* __restrict__ seq,
                                               const float* __restrict__ seqt,
                                               const void* __restrict__ maskp,
                                               float* __restrict__ out) {
  __shared__ float red[8 * 512];  // per-warp partial kbar [w][h*256+d]
  __shared__ float lg[128];       // masked logits (2 heads x 64)
  __shared__ float wms[8][2], wss[8][2];
  __shared__ float mflag[64];
  __shared__ int smode;

  int b = blockIdx.x, t = threadIdx.x;
  int w = t >> 5, l = t & 31;

  if (t == 0) {
    const unsigned int* mw = (const unsigned int*)maskp;
    int isInt = 1, isFloat = 1;
    for (int i = 0; i < 32; i++) {
      unsigned v = mw[i];
      if (v > 1u) isInt = 0;
      if (v != 0u && v != 0x3F800000u) isFloat = 0;
    }
    smode = isInt ? 0 : (isFloat ? 1 : 2);
  }

  const float4* qv = (const float4*)(g_qk + b * 512);
  float4 qA0 = qv[l], qB0 = qv[32 + l], qA1 = qv[64 + l], qB1 = qv[96 + l];
  __syncthreads();
  if (t < 64) {
    int mode = smode, m;
    if (mode == 0)      m = ((const int*)maskp)[b * 64 + t] != 0;
    else if (mode == 1) m = ((const float*)maskp)[b * 64 + t] != 0.f;
    else                m = ((const unsigned char*)maskp)[b * 64 + t] != 0;
    mflag[t] = m ? 1.f : 0.f;
  }
  __syncthreads();

  const float4* s4 = (const float4*)(seq + (long long)b * 8192);
  const float4* st4 = (const float4*)(seqt + (long long)b * 8192);
  const float sc = 0.08838834764831843f;  // 1/sqrt(128)

  float m0 = -1e30f, m1 = -1e30f, ss0 = 0.f, ss1 = 0.f;
  float4 aA0 = {0, 0, 0, 0}, aB0 = {0, 0, 0, 0};
  float4 aA1 = {0, 0, 0, 0}, aB1 = {0, 0, 0, 0};

#pragma unroll
  for (int i = 0; i < 8; i++) {
    int e = t + i * 256;
    int n = w + 8 * i;
    float4 kA = s4[e], kB = st4[e];
    float s0 = kA.x * qA0.x + kA.y * qA0.y + kA.z * qA0.z + kA.w * qA0.w +
               kB.x * qB0.x + kB.y * qB0.y + kB.z * qB0.z + kB.w * qB0.w;
    float s1 = kA.x * qA1.x + kA.y * qA1.y + kA.z * qA1.z + kA.w * qA1.w +
               kB.x * qB1.x + kB.y * qB1.y + kB.z * qB1.z + kB.w * qB1.w;
#pragma unroll
    for (int o = 16; o; o >>= 1) {
      s0 += __shfl_xor_sync(0xffffffffu, s0, o);
      s1 += __shfl_xor_sync(0xffffffffu, s1, o);
    }
    int masked = (mflag[n] != 0.f);
    float x0 = masked ? -1e10f : s0 * sc;
    float x1 = masked ? -1e10f : s1 * sc;
    if (l == 0) { lg[n] = x0; lg[64 + n] = x1; }
    // online softmax update, head 0
    float nm0 = fmaxf(m0, x0);
    float c0 = __expf(m0 - nm0), p0 = __expf(x0 - nm0);
    ss0 = ss0 * c0 + p0;
    aA0.x = aA0.x * c0 + p0 * kA.x; aA0.y = aA0.y * c0 + p0 * kA.y;
    aA0.z = aA0.z * c0 + p0 * kA.z; aA0.w = aA0.w * c0 + p0 * kA.w;
    aB0.x = aB0.x * c0 + p0 * kB.x; aB0.y = aB0.y * c0 + p0 * kB.y;
    aB0.z = aB0.z * c0 + p0 * kB.z; aB0.w = aB0.w * c0 + p0 * kB.w;
    m0 = nm0;
    // head 1
    float nm1 = fmaxf(m1, x1);
    float c1 = __expf(m1 - nm1), p1 = __expf(x1 - nm1);
    ss1 = ss1 * c1 + p1;
    aA1.x = aA1.x * c1 + p1 * kA.x; aA1.y = aA1.y * c1 + p1 * kA.y;
    aA1.z = aA1.z * c1 + p1 * kA.z; aA1.w = aA1.w * c1 + p1 * kA.w;
    aB1.x = aB1.x * c1 + p1 * kB.x; aB1.y = aB1.y * c1 + p1 * kB.y;
    aB1.z = aB1.z * c1 + p1 * kB.z; aB1.w = aB1.w * c1 + p1 * kB.w;
    m1 = nm1;
  }

  *(float4*)&red[w * 512 + 4 * l] = aA0;
  *(float4*)&red[w * 512 + 128 + 4 * l] = aB0;
  *(float4*)&red[w * 512 + 256 + 4 * l] = aA1;
  *(float4*)&red[w * 512 + 384 + 4 * l] = aB1;
  if (l == 0) { wms[w][0] = m0; wms[w][1] = m1; wss[w][0] = ss0; wss[w][1] = ss1; }
  __syncthreads();

  // Combine across 8 warps. Thread t owns dim t for both heads.
  float gm0 = -1e30f, gm1 = -1e30f;
#pragma unroll
  for (int j = 0; j < 8; j++) {
    gm0 = fmaxf(gm0, wms[j][0]);
    gm1 = fmaxf(gm1, wms[j][1]);
  }
  float gs0 = 0.f, gs1 = 0.f, kb0 = 0.f, kb1 = 0.f;
#pragma unroll
  for (int j = 0; j < 8; j++) {
    float e0 = __expf(wms[j][0] - gm0), e1 = __expf(wms[j][1] - gm1);
    gs0 += wss[j][0] * e0;
    gs1 += wss[j][1] * e1;
    kb0 += red[j * 512 + t] * e0;
    kb1 += red[j * 512 + 256 + t] * e1;
  }
  g_kbar[b * 512 + t] = kb0 / gs0;
  g_kbar[b * 512 + 256 + t] = kb1 / gs1;

  // attn weights output: warp 0 -> head 0, warp 1 -> head 1
  if (w < 2) {
    float gm = (w == 0) ? gm0 : gm1;
    float gi = 1.f / ((w == 0) ? gs0 : gs1);
    out[524288 + (w * 4096 + b) * 64 + l] = __expf(lg[w * 64 + l] - gm) * gi;
    out[524288 + (w * 4096 + b) * 64 + 32 + l] = __expf(lg[w * 64 + 32 + l] - gm) * gi;
  }
}

// ---------------------------------------------------------------------------
// K3a: g_x = kbar(4096x512) @ P(512x256) + fc_b + q_in. BM=64 BN=64 BK=16,
// 4x4/thread, f32x2 + prefetch. grid (64,4)=256.
// ---------------------------------------------------------------------------
__global__ __launch_bounds__(256) void k3a_fc(const float* __restrict__ src,
                                              const float* __restrict__ srct,
                                              const float* __restrict__ fc_b) {
  __shared__ float As[16][64];
  __shared__ float Bs[16][64];
  int bm = blockIdx.x * 64, bn = blockIdx.y * 64;
  int t = threadIdx.x;
  int ty = t >> 4, tx = t & 15;  // 16 row-groups of 4, 16 col-groups of 4
  ull acc[4][2];
#pragma unroll
  for (int i = 0; i < 4; i++) { acc[i][0] = 0ull; acc[i][1] = 0ull; }

  float4 pa, pb;
  auto loadA = [&](int kt) {
    int r = t >> 2, g = t & 3;
    pa = *(const float4*)&g_kbar[(bm + r) * 512 + kt * 16 + g * 4];
  };
  auto loadB = [&](int kt) {
    int kk = t >> 4, n4 = t & 15;
    pb = *(const float4*)&g_P[(kt * 16 + kk) * 256 + bn + n4 * 4];
  };
  loadA(0); loadB(0);
  for (int kt = 0; kt < 32; kt++) {
    {
      int r = t >> 2, g = t & 3;
      As[g * 4 + 0][r] = pa.x; As[g * 4 + 1][r] = pa.y;
      As[g * 4 + 2][r] = pa.z; As[g * 4 + 3][r] = pa.w;
    }
    { int kk = t >> 4, n4 = t & 15; *(float4*)&Bs[kk][n4 * 4] = pb; }
    __syncthreads();
    if (kt < 31) { loadA(kt + 1); loadB(kt + 1); }
#pragma unroll
    for (int kk = 0; kk < 16; kk++) {
      float4 a0 = *(const float4*)&As[kk][ty * 4];
      ull A[4] = {pk2(a0.x), pk2(a0.y), pk2(a0.z), pk2(a0.w)};
      ull b0 = *(const ull*)&Bs[kk][tx * 4];
      ull b1 = *(const ull*)&Bs[kk][tx * 4 + 2];
#pragma unroll
      for (int i = 0; i < 4; i++) { fma2(acc[i][0], A[i], b0); fma2(acc[i][1], A[i], b1); }
    }
    __syncthreads();
  }
#pragma unroll
  for (int i = 0; i < 4; i++) {
    int r = bm + ty * 4 + i;
    float2 p0 = upk(acc[i][0]), p1 = upk(acc[i][1]);
    float o[4] = {p0.x, p0.y, p1.x, p1.y};
    float4 v;
    float* vp = &v.x;
#pragma unroll
    for (int j = 0; j < 4; j++) {
      int c = bn + tx * 4 + j;
      float resid = (c < 128) ? src[r * 128 + c] : srct[r * 128 + c - 128];
      vp[j] = o[j] + fc_b[c] + resid;
    }
    *(float4*)&g_x[r * 256 + bn + tx * 4] = v;
  }
}

// ---------------------------------------------------------------------------
// K3b: per 16-batch tile: LN(g_x) -> xh, src append, GEMM2 relu, GEMM3 -> out.
// grid 256.
// ---------------------------------------------------------------------------
__global__ __launch_bounds__(256) void k3b_ffn(
    const float* __restrict__ src, const float* __restrict__ ln_g,
    const float* __restrict__ ln_b, const float* __restrict__ fc1_w,
    const float* __restrict__ fc1_b, const float* __restrict__ fc2_w,
    const float* __restrict__ fc2_b, float* __restrict__ out) {
  extern __shared__ float sm3[];
  float* xh = sm3;           // 16 x 388 (padded)
  float* Bs = xh + 16 * 388; // 16 x 128
  float* hm = Bs + 2048;     // 16 x 132 (padded)
  int bb = blockIdx.x * 16;
  int t = threadIdx.x;
  int w = t >> 5, l = t & 31;

  // load g_x tile (16x256) and src (16x128)
#pragma unroll
  for (int i = 0; i < 4; i++) {
    int e = t + i * 256, r = e >> 6, c4 = e & 63;
    *(float4*)&xh[r * 388 + c4 * 4] = *(const float4*)&g_x[(bb + r) * 256 + c4 * 4];
  }
#pragma unroll
  for (int i = 0; i < 2; i++) {
    int e = t + i * 256, r = e >> 5, c4 = e & 31;
    *(float4*)&xh[r * 388 + 256 + c4 * 4] = *(const float4*)&src[(bb + r) * 128 + c4 * 4];
  }
  __syncthreads();

  // LayerNorm over cols 0..255 in place (warp w: rows w*2, w*2+1)
#pragma unroll
  for (int rr = 0; rr < 2; rr++) {
    int r = w * 2 + rr;
    float s1 = 0.f, s2 = 0.f;
#pragma unroll
    for (int q = 0; q < 8; q++) {
      float x = xh[r * 388 + l + 32 * q];
      s1 += x; s2 += x * x;
    }
#pragma unroll
    for (int o = 16; o; o >>= 1) {
      s1 += __shfl_xor_sync(0xffffffffu, s1, o);
      s2 += __shfl_xor_sync(0xffffffffu, s2, o);
    }
    float mu = s1 * (1.f / 256.f);
    float var = s2 * (1.f / 256.f) - mu * mu;
    float rs = rsqrtf(var + 1e-5f);
#pragma unroll
    for (int q = 0; q < 8; q++) {
      int c = l + 32 * q;
      float x = xh[r * 388 + c];
      xh[r * 388 + c] = (x - mu) * rs * ln_g[c] + ln_b[c];
    }
  }
  __syncthreads();

  int ty2 = w, tx2 = l;  // rows ty2*2.., cols tx2*4..
  // ---- GEMM2: xh(16x384) @ fc1_w(384x128) + relu -> hm ----
  {
    ull acc[2][2];
    acc[0][0] = acc[0][1] = acc[1][0] = acc[1][1] = 0ull;
    float4 pb[2];
    auto loadB = [&](int kt) {
#pragma unroll
      for (int i = 0; i < 2; i++) {
        int e = t + i * 256, kk = e >> 5, c4 = e & 31;
        pb[i] = *(const float4*)&fc1_w[(kt * 16 + kk) * 128 + c4 * 4];
      }
    };
    loadB(0);
    for (int kt = 0; kt < 24; kt++) {
#pragma unroll
      for (int i = 0; i < 2; i++) {
        int e = t + i * 256, kk = e >> 5, c4 = e & 31;
        *(float4*)&Bs[kk * 128 + c4 * 4] = pb[i];
      }
      __syncthreads();
      if (kt < 23) loadB(kt + 1);
#pragma unroll
      for (int kk = 0; kk < 16; kk++) {
        int k = kt * 16 + kk;
        ull A0 = pk2(xh[(ty2 * 2 + 0) * 388 + k]);
        ull A1 = pk2(xh[(ty2 * 2 + 1) * 388 + k]);
        ull b0 = *(const ull*)&Bs[kk * 128 + tx2 * 4];
        ull b1 = *(const ull*)&Bs[kk * 128 + tx2 * 4 + 2];
        fma2(acc[0][0], A0, b0); fma2(acc[0][1], A0, b1);
        fma2(acc[1][0], A1, b0); fma2(acc[1][1], A1, b1);
      }
      __syncthreads();
    }
#pragma unroll
    for (int i = 0; i < 2; i++) {
      float2 p0 = upk(acc[i][0]), p1 = upk(acc[i][1]);
      int r = ty2 * 2 + i, c = tx2 * 4;
      hm[r * 132 + c + 0] = fmaxf(p0.x + fc1_b[c + 0], 0.f);
      hm[r * 132 + c + 1] = fmaxf(p0.y + fc1_b[c + 1], 0.f);
      hm[r * 132 + c + 2] = fmaxf(p1.x + fc1_b[c + 2], 0.f);
      hm[r * 132 + c + 3] = fmaxf(p1.y + fc1_b[c + 3], 0.f);
    }
  }
  __syncthreads();

  // ---- GEMM3: hm(16x128) @ fc2_w(128x128) -> out ----
  {
    ull acc[2][2];
    acc[0][0] = acc[0][1] = acc[1][0] = acc[1][1] = 0ull;
    float4 pb[2];
    auto loadB = [&](int kt) {
#pragma unroll
      for (int i = 0; i < 2; i++) {
        int e = t + i * 256, kk = e >> 5, c4 = e & 31;
        pb[i] = *(const float4*)&fc2_w[(kt * 16 + kk) * 128 + c4 * 4];
      }
    };
    loadB(0);
    for (int kt = 0; kt < 8; kt++) {
#pragma unroll
      for (int i = 0; i < 2; i++) {
        int e = t + i * 256, kk = e >> 5, c4 = e & 31;
        *(float4*)&Bs[kk * 128 + c4 * 4] = pb[i];
      }
      __syncthreads();
      if (kt < 7) loadB(kt + 1);
#pragma unroll
      for (int kk = 0; kk < 16; kk++) {
        int k = kt * 16 + kk;
        ull A0 = pk2(hm[(ty2 * 2 + 0) * 132 + k]);
        ull A1 = pk2(hm[(ty2 * 2 + 1) * 132 + k]);
        ull b0 = *(const ull*)&Bs[kk * 128 + tx2 * 4];
        ull b1 = *(const ull*)&Bs[kk * 128 + tx2 * 4 + 2];
        fma2(acc[0][0], A0, b0); fma2(acc[0][1], A0, b1);
        fma2(acc[1][0], A1, b0); fma2(acc[1][1], A1, b1);
      }
      __syncthreads();
    }
#pragma unroll
    for (int i = 0; i < 2; i++) {
      float2 p0 = upk(acc[i][0]), p1 = upk(acc[i][1]);
      int r = bb + ty2 * 2 + i, c = tx2 * 4;
      float4 v = make_float4(p0.x + fc2_b[c], p0.y + fc2_b[c + 1],
                             p1.x + fc2_b[c + 2], p1.y + fc2_b[c + 3]);
      *(float4*)&out[r * 128 + c] = v;
    }
  }
}

// ---------------------------------------------------------------------------
extern "C" void kernel_launch(void* const* d_in, const int* in_sizes, int n_in,
                              void* d_out, int out_size) {
  const float* src   = (const float*)d_in[0];
  const float* src_t = (const float*)d_in[1];
  const float* seq   = (const float*)d_in[2];
  const float* seq_t = (const float*)d_in[3];
  const void*  mask  = d_in[4];
  const float* w_qs  = (const float*)d_in[5];
  const float* w_ks  = (const float*)d_in[6];
  const float* w_vs  = (const float*)d_in[7];
  const float* fc_w  = (const float*)d_in[8];
  const float* fc_b  = (const float*)d_in[9];
  const float* ln_g  = (const float*)d_in[10];
  const float* ln_b  = (const float*)d_in[11];
  const float* fc1_w = (const float*)d_in[12];
  const float* fc1_b = (const float*)d_in[13];
  const float* fc2_w = (const float*)d_in[14];
  const float* fc2_b = (const float*)d_in[15];
  float* out = (float*)d_out;

  const int K3B_SMEM = (16 * 388 + 2048 + 16 * 132) * 4;  // 41472 B
  cudaFuncSetAttribute(k3b_ffn, cudaFuncAttributeMaxDynamicSharedMemorySize, K3B_SMEM);

  k0_precompute<<<1024, 256>>>(w_qs, w_ks, w_vs, fc_w);
  k1_qk<<<dim3(64, 4), 256>>>(src, src_t);
  k2_attn<<<4096, 256>>>(seq, seq_t, mask, out);
  k3a_fc<<<dim3(64, 4), 256>>>(src, src_t, fc_b);
  k3b_ffn<<<256, 256, K3B_SMEM>>>(src, ln_g, ln_b, fc1_w, fc1_b, fc2_w, fc2_b,
                                  out);
}

// round 5
// speedup vs baseline: 1.0799x; 1.0037x over previous
#include <cuda_runtime.h>

// B=4096, N=64, FEAT=128, TIME=128, D_MODEL=256, N_HEAD=2, D_K=128
typedef unsigned long long ull;

__device__ float g_M[256 * 512];     // M[k][h*256+c]
__device__ float g_P[512 * 256];     // P[(h*256+i)][j]
__device__ float g_qk[4096 * 512];   // qk[b][h*256+c]
__device__ float g_kbar[4096 * 512]; // kbar[b][h*256+i]
__device__ float g_x[4096 * 256];    // fc_out + q_in residual (pre-LN)

__device__ __forceinline__ ull pk2(float x) {
  ull r; asm("mov.b64 %0,{%1,%1};" : "=l"(r) : "f"(x)); return r;
}
__device__ __forceinline__ void fma2(ull& d, ull a, ull b) {
  asm("fma.rn.f32x2 %0,%1,%2,%0;" : "+l"(d) : "l"(a), "l"(b));
}
__device__ __forceinline__ float2 upk(ull v) {
  float2 f; asm("mov.b64 {%0,%1},%2;" : "=f"(f.x), "=f"(f.y) : "l"(v)); return f;
}

// ---------------------------------------------------------------------------
// K0: precompute M (256x512) and P (512x256).
// ---------------------------------------------------------------------------
__global__ __launch_bounds__(256) void k0_precompute(
    const float* __restrict__ w_qs, const float* __restrict__ w_ks,
    const float* __restrict__ w_vs, const float* __restrict__ fc_w) {
  int o = blockIdx.x * 256 + threadIdx.x;
  if (o < 131072) {
    int k = o >> 9, j = o & 511, h = j >> 8, c = j & 255;
    const float* a = w_qs + k * 256 + h * 128;
    const float* b = w_ks + c * 256 + h * 128;
    float s = 0.f;
#pragma unroll 8
    for (int d = 0; d < 128; d++) s += a[d] * b[d];
    g_M[o] = s;
  } else {
    int o2 = o - 131072;
    int r = o2 >> 8, j = o2 & 255, h = r >> 8, i = r & 255;
    const float* a = w_vs + i * 256 + h * 128;
    float s = 0.f;
#pragma unroll 8
    for (int d = 0; d < 128; d++) s += a[d] * fc_w[(h * 128 + d) * 256 + j];
    g_P[o2] = s;
  }
}

// ---------------------------------------------------------------------------
// K1: qk = Q_in(4096x256) @ M(256x512). BM=64 BN=128 BK=32, 4x8/thread,
// f32x2 + prefetch. grid (64,4)=256.
// ---------------------------------------------------------------------------
__global__ __launch_bounds__(256) void k1_qk(const float* __restrict__ src,
                                             const float* __restrict__ srct) {
  __shared__ float As[32][64];
  __shared__ float Bs[32][128];
  int bm = blockIdx.x * 64, bn = blockIdx.y * 128;
  int t = threadIdx.x;
  int ty = t >> 4, tx = t & 15;
  ull acc[4][4];
#pragma unroll
  for (int i = 0; i < 4; i++)
#pragma unroll
    for (int j = 0; j < 4; j++) acc[i][j] = 0ull;

  float4 pa[2], pb[4];
  auto loadA = [&](int kt) {
#pragma unroll
    for (int i = 0; i < 2; i++) {
      int e = t + i * 256, r = e >> 3, g = e & 7, k = kt * 32 + g * 4;
      pa[i] = (k < 128) ? *(const float4*)&src[(bm + r) * 128 + k]
                        : *(const float4*)&srct[(bm + r) * 128 + k - 128];
    }
  };
  auto loadB = [&](int kt) {
#pragma unroll
    for (int i = 0; i < 4; i++) {
      int e = t + i * 256, kk = e >> 5, n4 = e & 31;
      pb[i] = *(const float4*)&g_M[(kt * 32 + kk) * 512 + bn + n4 * 4];
    }
  };
  loadA(0); loadB(0);
  for (int kt = 0; kt < 8; kt++) {
#pragma unroll
    for (int i = 0; i < 2; i++) {
      int e = t + i * 256, r = e >> 3, g = e & 7;
      As[g * 4 + 0][r] = pa[i].x; As[g * 4 + 1][r] = pa[i].y;
      As[g * 4 + 2][r] = pa[i].z; As[g * 4 + 3][r] = pa[i].w;
    }
#pragma unroll
    for (int i = 0; i < 4; i++) {
      int e = t + i * 256, kk = e >> 5, n4 = e & 31;
      *(float4*)&Bs[kk][n4 * 4] = pb[i];
    }
    __syncthreads();
    if (kt < 7) { loadA(kt + 1); loadB(kt + 1); }
#pragma unroll
    for (int kk = 0; kk < 32; kk++) {
      float4 a0 = *(const float4*)&As[kk][ty * 4];
      ull A[4] = {pk2(a0.x), pk2(a0.y), pk2(a0.z), pk2(a0.w)};
      ull b[4];
#pragma unroll
      for (int j = 0; j < 4; j++) b[j] = *(const ull*)&Bs[kk][tx * 8 + 2 * j];
#pragma unroll
      for (int i = 0; i < 4; i++)
#pragma unroll
        for (int j = 0; j < 4; j++) fma2(acc[i][j], A[i], b[j]);
    }
    __syncthreads();
  }
#pragma unroll
  for (int i = 0; i < 4; i++) {
    int r = bm + ty * 4 + i;
    float2 p0 = upk(acc[i][0]), p1 = upk(acc[i][1]);
    float2 p2 = upk(acc[i][2]), p3 = upk(acc[i][3]);
    *(float4*)&g_qk[r * 512 + bn + tx * 8] = make_float4(p0.x, p0.y, p1.x, p1.y);
    *(float4*)&g_qk[r * 512 + bn + tx * 8 + 4] = make_float4(p2.x, p2.y, p3.x, p3.y);
  }
}

// ---------------------------------------------------------------------------
// K2: attention, front-batched loads. One block per batch. All 16 key-float4s
// loaded to registers up front (MLP=16), two-pass softmax, weighted sum from
// registers, 8-warp combine.
// ---------------------------------------------------------------------------
__global__ __launch_bounds__(256) void k2_attn(const float* __restrict__ seq,
                                               const float* __restrict__ seqt,
                                               const void* __restrict__ maskp,
                                               float* __restrict__ out) {
  __shared__ float red[8 * 512];  // per-warp partial kbar
  __shared__ float aw[128];       // attn weights (2 heads x 64)
  __shared__ float mflag[64];
  __shared__ int smode;

  int b = blockIdx.x, t = threadIdx.x;
  int w = t >> 5, l = t & 31;

  // Front-batched key loads: 16 independent LDG.128.
  const float4* s4 = (const float4*)(seq + (long long)b * 8192);
  const float4* st4 = (const float4*)(seqt + (long long)b * 8192);
  float4 kA[8], kB[8];
#pragma unroll
  for (int i = 0; i < 8; i++) kA[i] = s4[t + i * 256];
#pragma unroll
  for (int i = 0; i < 8; i++) kB[i] = st4[t + i * 256];

  const float4* qv = (const float4*)(g_qk + b * 512);
  float4 qA0 = qv[l], qB0 = qv[32 + l], qA1 = qv[64 + l], qB1 = qv[96 + l];

  if (t == 0) {
    const unsigned int* mw = (const unsigned int*)maskp;
    int isInt = 1, isFloat = 1;
    for (int i = 0; i < 32; i++) {
      unsigned v = mw[i];
      if (v > 1u) isInt = 0;
      if (v != 0u && v != 0x3F800000u) isFloat = 0;
    }
    smode = isInt ? 0 : (isFloat ? 1 : 2);
  }
  __syncthreads();
  if (t < 64) {
    int mode = smode, m;
    if (mode == 0)      m = ((const int*)maskp)[b * 64 + t] != 0;
    else if (mode == 1) m = ((const float*)maskp)[b * 64 + t] != 0.f;
    else                m = ((const unsigned char*)maskp)[b * 64 + t] != 0;
    mflag[t] = m ? 1.f : 0.f;
  }
  __syncthreads();

  const float sc = 0.08838834764831843f;  // 1/sqrt(128)
  // Logits (key n = w + 8*i), reuse aw buffer for logits.
#pragma unroll
  for (int i = 0; i < 8; i++) {
    float s0 = kA[i].x * qA0.x + kA[i].y * qA0.y + kA[i].z * qA0.z + kA[i].w * qA0.w +
               kB[i].x * qB0.x + kB[i].y * qB0.y + kB[i].z * qB0.z + kB[i].w * qB0.w;
    float s1 = kA[i].x * qA1.x + kA[i].y * qA1.y + kA[i].z * qA1.z + kA[i].w * qA1.w +
               kB[i].x * qB1.x + kB[i].y * qB1.y + kB[i].z * qB1.z + kB[i].w * qB1.w;
#pragma unroll
    for (int o = 16; o; o >>= 1) {
      s0 += __shfl_xor_sync(0xffffffffu, s0, o);
      s1 += __shfl_xor_sync(0xffffffffu, s1, o);
    }
    if (l == 0) {
      int n = w + 8 * i;
      int masked = (mflag[n] != 0.f);
      aw[n] = masked ? -1e10f : s0 * sc;
      aw[64 + n] = masked ? -1e10f : s1 * sc;
    }
  }
  __syncthreads();

  // Softmax (warp 0: head 0, warp 1: head 1), write weights + attn output.
  if (w < 2) {
    float x0 = aw[w * 64 + l], x1 = aw[w * 64 + 32 + l];
    float m = fmaxf(x0, x1);
#pragma unroll
    for (int o = 16; o; o >>= 1) m = fmaxf(m, __shfl_xor_sync(0xffffffffu, m, o));
    float e0 = __expf(x0 - m), e1 = __expf(x1 - m);
    float s = e0 + e1;
#pragma unroll
    for (int o = 16; o; o >>= 1) s += __shfl_xor_sync(0xffffffffu, s, o);
    float inv = 1.f / s;
    float a0 = e0 * inv, a1 = e1 * inv;
    aw[w * 64 + l] = a0;
    aw[w * 64 + 32 + l] = a1;
    out[524288 + (w * 4096 + b) * 64 + l] = a0;
    out[524288 + (w * 4096 + b) * 64 + 32 + l] = a1;
  }
  __syncthreads();

  // Weighted key sums from registers.
  float4 aA0 = {0,0,0,0}, aB0 = {0,0,0,0}, aA1 = {0,0,0,0}, aB1 = {0,0,0,0};
#pragma unroll
  for (int i = 0; i < 8; i++) {
    int n = w + 8 * i;
    float a0 = aw[n], a1 = aw[64 + n];
    aA0.x += a0 * kA[i].x; aA0.y += a0 * kA[i].y; aA0.z += a0 * kA[i].z; aA0.w += a0 * kA[i].w;
    aB0.x += a0 * kB[i].x; aB0.y += a0 * kB[i].y; aB0.z += a0 * kB[i].z; aB0.w += a0 * kB[i].w;
    aA1.x += a1 * kA[i].x; aA1.y += a1 * kA[i].y; aA1.z += a1 * kA[i].z; aA1.w += a1 * kA[i].w;
    aB1.x += a1 * kB[i].x; aB1.y += a1 * kB[i].y; aB1.z += a1 * kB[i].z; aB1.w += a1 * kB[i].w;
  }
  *(float4*)&red[w * 512 + 4 * l] = aA0;
  *(float4*)&red[w * 512 + 128 + 4 * l] = aB0;
  *(float4*)&red[w * 512 + 256 + 4 * l] = aA1;
  *(float4*)&red[w * 512 + 384 + 4 * l] = aB1;
  __syncthreads();

  // Plain sum across 8 warps; thread t owns dim t of both heads.
  float kb0 = 0.f, kb1 = 0.f;
#pragma unroll
  for (int j = 0; j < 8; j++) {
    kb0 += red[j * 512 + t];
    kb1 += red[j * 512 + 256 + t];
  }
  g_kbar[b * 512 + t] = kb0;
  g_kbar[b * 512 + 256 + t] = kb1;
}

// ---------------------------------------------------------------------------
// K3a: g_x = kbar(4096x512) @ P(512x256) + fc_b + q_in. BM=64 BN=64 BK=32,
// 4x4/thread, f32x2 + prefetch. grid (64,4)=256.
// ---------------------------------------------------------------------------
__global__ __launch_bounds__(256) void k3a_fc(const float* __restrict__ src,
                                              const float* __restrict__ srct,
                                              const float* __restrict__ fc_b) {
  __shared__ float As[32][64];
  __shared__ float Bs[32][64];
  int bm = blockIdx.x * 64, bn = blockIdx.y * 64;
  int t = threadIdx.x;
  int ty = t >> 4, tx = t & 15;
  ull acc[4][2];
#pragma unroll
  for (int i = 0; i < 4; i++) { acc[i][0] = 0ull; acc[i][1] = 0ull; }

  float4 pa[2], pb[2];
  auto loadA = [&](int kt) {
#pragma unroll
    for (int i = 0; i < 2; i++) {
      int e = t + i * 256, r = e >> 3, g = e & 7;
      pa[i] = *(const float4*)&g_kbar[(bm + r) * 512 + kt * 32 + g * 4];
    }
  };
  auto loadB = [&](int kt) {
#pragma unroll
    for (int i = 0; i < 2; i++) {
      int e = t + i * 256, kk = e >> 4, n4 = e & 15;
      pb[i] = *(const float4*)&g_P[(kt * 32 + kk) * 256 + bn + n4 * 4];
    }
  };
  loadA(0); loadB(0);
  for (int kt = 0; kt < 16; kt++) {
#pragma unroll
    for (int i = 0; i < 2; i++) {
      int e = t + i * 256, r = e >> 3, g = e & 7;
      As[g * 4 + 0][r] = pa[i].x; As[g * 4 + 1][r] = pa[i].y;
      As[g * 4 + 2][r] = pa[i].z; As[g * 4 + 3][r] = pa[i].w;
    }
#pragma unroll
    for (int i = 0; i < 2; i++) {
      int e = t + i * 256, kk = e >> 4, n4 = e & 15;
      *(float4*)&Bs[kk][n4 * 4] = pb[i];
    }
    __syncthreads();
    if (kt < 15) { loadA(kt + 1); loadB(kt + 1); }
#pragma unroll
    for (int kk = 0; kk < 32; kk++) {
      float4 a0 = *(const float4*)&As[kk][ty * 4];
      ull A[4] = {pk2(a0.x), pk2(a0.y), pk2(a0.z), pk2(a0.w)};
      ull b0 = *(const ull*)&Bs[kk][tx * 4];
      ull b1 = *(const ull*)&Bs[kk][tx * 4 + 2];
#pragma unroll
      for (int i = 0; i < 4; i++) { fma2(acc[i][0], A[i], b0); fma2(acc[i][1], A[i], b1); }
    }
    __syncthreads();
  }
#pragma unroll
  for (int i = 0; i < 4; i++) {
    int r = bm + ty * 4 + i;
    float2 p0 = upk(acc[i][0]), p1 = upk(acc[i][1]);
    float o[4] = {p0.x, p0.y, p1.x, p1.y};
    float4 v;
    float* vp = &v.x;
#pragma unroll
    for (int j = 0; j < 4; j++) {
      int c = bn + tx * 4 + j;
      float resid = (c < 128) ? src[r * 128 + c] : srct[r * 128 + c - 128];
      vp[j] = o[j] + fc_b[c] + resid;
    }
    *(float4*)&g_x[r * 256 + bn + tx * 4] = v;
  }
}

// ---------------------------------------------------------------------------
// K3b: per 16-batch tile: LN(g_x) -> xh, src append, GEMM2 relu, GEMM3 -> out.
// BK=32. grid 256.
// ---------------------------------------------------------------------------
__global__ __launch_bounds__(256) void k3b_ffn(
    const float* __restrict__ src, const float* __restrict__ ln_g,
    const float* __restrict__ ln_b, const float* __restrict__ fc1_w,
    const float* __restrict__ fc1_b, const float* __restrict__ fc2_w,
    const float* __restrict__ fc2_b, float* __restrict__ out) {
  extern __shared__ float sm3[];
  float* xh = sm3;           // 16 x 388 (padded)
  float* Bs = xh + 16 * 388; // 32 x 128
  float* hm = Bs + 4096;     // 16 x 132 (padded)
  int bb = blockIdx.x * 16;
  int t = threadIdx.x;
  int w = t >> 5, l = t & 31;

#pragma unroll
  for (int i = 0; i < 4; i++) {
    int e = t + i * 256, r = e >> 6, c4 = e & 63;
    *(float4*)&xh[r * 388 + c4 * 4] = *(const float4*)&g_x[(bb + r) * 256 + c4 * 4];
  }
#pragma unroll
  for (int i = 0; i < 2; i++) {
    int e = t + i * 256, r = e >> 5, c4 = e & 31;
    *(float4*)&xh[r * 388 + 256 + c4 * 4] = *(const float4*)&src[(bb + r) * 128 + c4 * 4];
  }
  __syncthreads();

  // LayerNorm over cols 0..255 (warp w: rows w*2, w*2+1)
#pragma unroll
  for (int rr = 0; rr < 2; rr++) {
    int r = w * 2 + rr;
    float s1 = 0.f, s2 = 0.f;
#pragma unroll
    for (int q = 0; q < 8; q++) {
      float x = xh[r * 388 + l + 32 * q];
      s1 += x; s2 += x * x;
    }
#pragma unroll
    for (int o = 16; o; o >>= 1) {
      s1 += __shfl_xor_sync(0xffffffffu, s1, o);
      s2 += __shfl_xor_sync(0xffffffffu, s2, o);
    }
    float mu = s1 * (1.f / 256.f);
    float var = s2 * (1.f / 256.f) - mu * mu;
    float rs = rsqrtf(var + 1e-5f);
#pragma unroll
    for (int q = 0; q < 8; q++) {
      int c = l + 32 * q;
      float x = xh[r * 388 + c];
      xh[r * 388 + c] = (x - mu) * rs * ln_g[c] + ln_b[c];
    }
  }
  __syncthreads();

  int ty2 = w, tx2 = l;
  // ---- GEMM2: xh(16x384) @ fc1_w(384x128) + relu -> hm ----
  {
    ull acc[2][2];
    acc[0][0] = acc[0][1] = acc[1][0] = acc[1][1] = 0ull;
    float4 pb[4];
    auto loadB = [&](int kt) {
#pragma unroll
      for (int i = 0; i < 4; i++) {
        int e = t + i * 256, kk = e >> 5, c4 = e & 31;
        pb[i] = *(const float4*)&fc1_w[(kt * 32 + kk) * 128 + c4 * 4];
      }
    };
    loadB(0);
    for (int kt = 0; kt < 12; kt++) {
#pragma unroll
      for (int i = 0; i < 4; i++) {
        int e = t + i * 256, kk = e >> 5, c4 = e & 31;
        *(float4*)&Bs[kk * 128 + c4 * 4] = pb[i];
      }
      __syncthreads();
      if (kt < 11) loadB(kt + 1);
#pragma unroll
      for (int kk = 0; kk < 32; kk++) {
        int k = kt * 32 + kk;
        ull A0 = pk2(xh[(ty2 * 2 + 0) * 388 + k]);
        ull A1 = pk2(xh[(ty2 * 2 + 1) * 388 + k]);
        ull b0 = *(const ull*)&Bs[kk * 128 + tx2 * 4];
        ull b1 = *(const ull*)&Bs[kk * 128 + tx2 * 4 + 2];
        fma2(acc[0][0], A0, b0); fma2(acc[0][1], A0, b1);
        fma2(acc[1][0], A1, b0); fma2(acc[1][1], A1, b1);
      }
      __syncthreads();
    }
#pragma unroll
    for (int i = 0; i < 2; i++) {
      float2 p0 = upk(acc[i][0]), p1 = upk(acc[i][1]);
      int r = ty2 * 2 + i, c = tx2 * 4;
      hm[r * 132 + c + 0] = fmaxf(p0.x + fc1_b[c + 0], 0.f);
      hm[r * 132 + c + 1] = fmaxf(p0.y + fc1_b[c + 1], 0.f);
      hm[r * 132 + c + 2] = fmaxf(p1.x + fc1_b[c + 2], 0.f);
      hm[r * 132 + c + 3] = fmaxf(p1.y + fc1_b[c + 3], 0.f);
    }
  }
  __syncthreads();

  // ---- GEMM3: hm(16x128) @ fc2_w(128x128) -> out ----
  {
    ull acc[2][2];
    acc[0][0] = acc[0][1] = acc[1][0] = acc[1][1] = 0ull;
    float4 pb[4];
    auto loadB = [&](int kt) {
#pragma unroll
      for (int i = 0; i < 4; i++) {
        int e = t + i * 256, kk = e >> 5, c4 = e & 31;
        pb[i] = *(const float4*)&fc2_w[(kt * 32 + kk) * 128 + c4 * 4];
      }
    };
    loadB(0);
    for (int kt = 0; kt < 4; kt++) {
#pragma unroll
      for (int i = 0; i < 4; i++) {
        int e = t + i * 256, kk = e >> 5, c4 = e & 31;
        *(float4*)&Bs[kk * 128 + c4 * 4] = pb[i];
      }
      __syncthreads();
      if (kt < 3) loadB(kt + 1);
#pragma unroll
      for (int kk = 0; kk < 32; kk++) {
        int k = kt * 32 + kk;
        ull A0 = pk2(hm[(ty2 * 2 + 0) * 132 + k]);
        ull A1 = pk2(hm[(ty2 * 2 + 1) * 132 + k]);
        ull b0 = *(const ull*)&Bs[kk * 128 + tx2 * 4];
        ull b1 = *(const ull*)&Bs[kk * 128 + tx2 * 4 + 2];
        fma2(acc[0][0], A0, b0); fma2(acc[0][1], A0, b1);
        fma2(acc[1][0], A1, b0); fma2(acc[1][1], A1, b1);
      }
      __syncthreads();
    }
#pragma unroll
    for (int i = 0; i < 2; i++) {
      float2 p0 = upk(acc[i][0]), p1 = upk(acc[i][1]);
      int r = bb + ty2 * 2 + i, c = tx2 * 4;
      float4 v = make_float4(p0.x + fc2_b[c], p0.y + fc2_b[c + 1],
                             p1.x + fc2_b[c + 2], p1.y + fc2_b[c + 3]);
      *(float4*)&out[r * 128 + c] = v;
    }
  }
}

// ---------------------------------------------------------------------------
extern "C" void kernel_launch(void* const* d_in, const int* in_sizes, int n_in,
                              void* d_out, int out_size) {
  const float* src   = (const float*)d_in[0];
  const float* src_t = (const float*)d_in[1];
  const float* seq   = (const float*)d_in[2];
  const float* seq_t = (const float*)d_in[3];
  const void*  mask  = d_in[4];
  const float* w_qs  = (const float*)d_in[5];
  const float* w_ks  = (const float*)d_in[6];
  const float* w_vs  = (const float*)d_in[7];
  const float* fc_w  = (const float*)d_in[8];
  const float* fc_b  = (const float*)d_in[9];
  const float* ln_g  = (const float*)d_in[10];
  const float* ln_b  = (const float*)d_in[11];
  const float* fc1_w = (const float*)d_in[12];
  const float* fc1_b = (const float*)d_in[13];
  const float* fc2_w = (const float*)d_in[14];
  const float* fc2_b = (const float*)d_in[15];
  float* out = (float*)d_out;

  const int K3B_SMEM = (16 * 388 + 4096 + 16 * 132) * 4;  // 49664 B
  cudaFuncSetAttribute(k3b_ffn, cudaFuncAttributeMaxDynamicSharedMemorySize, K3B_SMEM);

  k0_precompute<<<1024, 256>>>(w_qs, w_ks, w_vs, fc_w);
  k1_qk<<<dim3(64, 4), 256>>>(src, src_t);
  k2_attn<<<4096, 256>>>(seq, seq_t, mask, out);
  k3a_fc<<<dim3(64, 4), 256>>>(src, src_t, fc_b);
  k3b_ffn<<<256, 256, K3B_SMEM>>>(src, ln_g, ln_b, fc1_w, fc1_b, fc2_w, fc2_b,
                                  out);
}

// round 7
// speedup vs baseline: 1.4655x; 1.3571x over previous
#include <cuda_runtime.h>

// B=4096, N=64, FEAT=128, TIME=128, D_MODEL=256, N_HEAD=2, D_K=128
typedef unsigned long long ull;

__device__ float g_M[256 * 512];     // M[k][h*256+c]
__device__ float g_P[512 * 256];     // P[(h*256+i)][j]
__device__ float g_qk[4096 * 512];   // qk[b][h*256+c]
__device__ float g_kbar[4096 * 512]; // kbar[b][h*256+i]
__device__ float g_x[4096 * 256];    // fc_out + q_in residual (pre-LN)

__device__ __forceinline__ ull pk2(float x) {
  ull r; asm("mov.b64 %0,{%1,%1};" : "=l"(r) : "f"(x)); return r;
}
__device__ __forceinline__ void fma2(ull& d, ull a, ull b) {
  asm("fma.rn.f32x2 %0,%1,%2,%0;" : "+l"(d) : "l"(a), "l"(b));
}
__device__ __forceinline__ float2 upk(ull v) {
  float2 f; asm("mov.b64 {%0,%1},%2;" : "=f"(f.x), "=f"(f.y) : "l"(v)); return f;
}

// ---------------------------------------------------------------------------
// K0: tiled precompute of M (256x512) and P (512x256), coalesced loads.
// grid 64: m<32 -> M tiles, m>=32 -> P tiles. Stride 132 (16B-aligned rows).
// ---------------------------------------------------------------------------
__global__ __launch_bounds__(256) void k0_precompute(
    const float* __restrict__ w_qs, const float* __restrict__ w_ks,
    const float* __restrict__ w_vs, const float* __restrict__ fc_w) {
  extern __shared__ float s0[];
  float* As = s0;              // 64 x 132 (padded, 16B-aligned rows)
  float* Bsm = s0 + 64 * 132;  // M: 64 x 132; P: 128 x 64
  int m = blockIdx.x, t = threadIdx.x;
  int ty = t >> 4, tx = t & 15;
  float acc[4][4] = {{0.f}};

  if (m < 32) {
    int h = m >> 4, kt = (m >> 2) & 3, ct = m & 3;
    // A = w_qs[kt*64+r][h*128+d], B = w_ks[ct*64+r][h*128+d] (both 64x128)
#pragma unroll
    for (int i = 0; i < 8; i++) {
      int e = t + i * 256, r = e >> 5, c4 = e & 31;
      *(float4*)&As[r * 132 + c4 * 4] =
          *(const float4*)&w_qs[(kt * 64 + r) * 256 + h * 128 + c4 * 4];
      *(float4*)&Bsm[r * 132 + c4 * 4] =
          *(const float4*)&w_ks[(ct * 64 + r) * 256 + h * 128 + c4 * 4];
    }
    __syncthreads();
    for (int d = 0; d < 128; d += 4) {
      float4 av[4], bv[4];
#pragma unroll
      for (int i = 0; i < 4; i++) av[i] = *(const float4*)&As[(ty * 4 + i) * 132 + d];
#pragma unroll
      for (int j = 0; j < 4; j++) bv[j] = *(const float4*)&Bsm[(tx * 4 + j) * 132 + d];
#pragma unroll
      for (int i = 0; i < 4; i++)
#pragma unroll
        for (int j = 0; j < 4; j++)
          acc[i][j] += av[i].x * bv[j].x + av[i].y * bv[j].y +
                       av[i].z * bv[j].z + av[i].w * bv[j].w;
    }
#pragma unroll
    for (int i = 0; i < 4; i++)
#pragma unroll
      for (int j = 0; j < 4; j++)
        g_M[(kt * 64 + ty * 4 + i) * 512 + h * 256 + ct * 64 + tx * 4 + j] = acc[i][j];
  } else {
    int m2 = m - 32;
    int h = m2 >> 4, it = (m2 >> 2) & 3, jt = m2 & 3;
    // A = w_vs[it*64+i][h*128+d] (64x128), B = fc_w[h*128+d][jt*64+j] (128x64)
#pragma unroll
    for (int i = 0; i < 8; i++) {
      int e = t + i * 256, r = e >> 5, c4 = e & 31;
      *(float4*)&As[r * 132 + c4 * 4] =
          *(const float4*)&w_vs[(it * 64 + r) * 256 + h * 128 + c4 * 4];
    }
#pragma unroll
    for (int i = 0; i < 8; i++) {
      int e = t + i * 256, d = e >> 4, j4 = e & 15;
      *(float4*)&Bsm[d * 64 + j4 * 4] =
          *(const float4*)&fc_w[(h * 128 + d) * 256 + jt * 64 + j4 * 4];
    }
    __syncthreads();
    for (int d = 0; d < 128; d++) {
      float4 bv = *(const float4*)&Bsm[d * 64 + tx * 4];
      float av[4];
#pragma unroll
      for (int i = 0; i < 4; i++) av[i] = As[(ty * 4 + i) * 132 + d];
#pragma unroll
      for (int i = 0; i < 4; i++) {
        acc[i][0] += av[i] * bv.x; acc[i][1] += av[i] * bv.y;
        acc[i][2] += av[i] * bv.z; acc[i][3] += av[i] * bv.w;
      }
    }
#pragma unroll
    for (int i = 0; i < 4; i++)
#pragma unroll
      for (int j = 0; j < 4; j++)
        g_P[(h * 256 + it * 64 + ty * 4 + i) * 256 + jt * 64 + tx * 4 + j] = acc[i][j];
  }
}

// ---------------------------------------------------------------------------
// K1: qk = Q_in(4096x256) @ M(256x512). BM=64 BN=128 BK=32, 4x8/thread,
// f32x2 + prefetch. grid (64,4)=256.
// ---------------------------------------------------------------------------
__global__ __launch_bounds__(256) void k1_qk(const float* __restrict__ src,
                                             const float* __restrict__ srct) {
  __shared__ float As[32][64];
  __shared__ float Bs[32][128];
  int bm = blockIdx.x * 64, bn = blockIdx.y * 128;
  int t = threadIdx.x;
  int ty = t >> 4, tx = t & 15;
  ull acc[4][4];
#pragma unroll
  for (int i = 0; i < 4; i++)
#pragma unroll
    for (int j = 0; j < 4; j++) acc[i][j] = 0ull;

  float4 pa[2], pb[4];
  auto loadA = [&](int kt) {
#pragma unroll
    for (int i = 0; i < 2; i++) {
      int e = t + i * 256, r = e >> 3, g = e & 7, k = kt * 32 + g * 4;
      pa[i] = (k < 128) ? *(const float4*)&src[(bm + r) * 128 + k]
                        : *(const float4*)&srct[(bm + r) * 128 + k - 128];
    }
  };
  auto loadB = [&](int kt) {
#pragma unroll
    for (int i = 0; i < 4; i++) {
      int e = t + i * 256, kk = e >> 5, n4 = e & 31;
      pb[i] = *(const float4*)&g_M[(kt * 32 + kk) * 512 + bn + n4 * 4];
    }
  };
  loadA(0); loadB(0);
  for (int kt = 0; kt < 8; kt++) {
#pragma unroll
    for (int i = 0; i < 2; i++) {
      int e = t + i * 256, r = e >> 3, g = e & 7;
      As[g * 4 + 0][r] = pa[i].x; As[g * 4 + 1][r] = pa[i].y;
      As[g * 4 + 2][r] = pa[i].z; As[g * 4 + 3][r] = pa[i].w;
    }
#pragma unroll
    for (int i = 0; i < 4; i++) {
      int e = t + i * 256, kk = e >> 5, n4 = e & 31;
      *(float4*)&Bs[kk][n4 * 4] = pb[i];
    }
    __syncthreads();
    if (kt < 7) { loadA(kt + 1); loadB(kt + 1); }
#pragma unroll
    for (int kk = 0; kk < 32; kk++) {
      float4 a0 = *(const float4*)&As[kk][ty * 4];
      ull A[4] = {pk2(a0.x), pk2(a0.y), pk2(a0.z), pk2(a0.w)};
      ull b[4];
#pragma unroll
      for (int j = 0; j < 4; j++) b[j] = *(const ull*)&Bs[kk][tx * 8 + 2 * j];
#pragma unroll
      for (int i = 0; i < 4; i++)
#pragma unroll
        for (int j = 0; j < 4; j++) fma2(acc[i][j], A[i], b[j]);
    }
    __syncthreads();
  }
#pragma unroll
  for (int i = 0; i < 4; i++) {
    int r = bm + ty * 4 + i;
    float2 p0 = upk(acc[i][0]), p1 = upk(acc[i][1]);
    float2 p2 = upk(acc[i][2]), p3 = upk(acc[i][3]);
    *(float4*)&g_qk[r * 512 + bn + tx * 8] = make_float4(p0.x, p0.y, p1.x, p1.y);
    *(float4*)&g_qk[r * 512 + bn + tx * 8 + 4] = make_float4(p2.x, p2.y, p3.x, p3.y);
  }
}

// ---------------------------------------------------------------------------
// K2: attention, low-register two-pass. Pass 1: logits from chunked loads.
// Pass 2: weighted sum re-reading keys (L2-hot). min 3 CTAs/SM.
// ---------------------------------------------------------------------------
__global__ __launch_bounds__(256, 3) void k2_attn(const float* __restrict__ seq,
                                                  const float* __restrict__ seqt,
                                                  const void* __restrict__ maskp,
                                                  float* __restrict__ out) {
  __shared__ float red[8 * 512];  // per-warp partial kbar
  __shared__ float aw[128];       // logits then attn weights (2 heads x 64)
  __shared__ float mflag[64];
  __shared__ int smode;

  int b = blockIdx.x, t = threadIdx.x;
  int w = t >> 5, l = t & 31;

  if (t == 0) {
    const unsigned int* mw = (const unsigned int*)maskp;
    int isInt = 1, isFloat = 1;
    for (int i = 0; i < 32; i++) {
      unsigned v = mw[i];
      if (v > 1u) isInt = 0;
      if (v != 0u && v != 0x3F800000u) isFloat = 0;
    }
    smode = isInt ? 0 : (isFloat ? 1 : 2);
  }

  const float4* qv = (const float4*)(g_qk + b * 512);
  float4 qA0 = qv[l], qB0 = qv[32 + l], qA1 = qv[64 + l], qB1 = qv[96 + l];
  __syncthreads();
  if (t < 64) {
    int mode = smode, m;
    if (mode == 0)      m = ((const int*)maskp)[b * 64 + t] != 0;
    else if (mode == 1) m = ((const float*)maskp)[b * 64 + t] != 0.f;
    else                m = ((const unsigned char*)maskp)[b * 64 + t] != 0;
    mflag[t] = m ? 1.f : 0.f;
  }
  __syncthreads();

  const float4* s4 = (const float4*)(seq + (long long)b * 8192);
  const float4* st4 = (const float4*)(seqt + (long long)b * 8192);
  const float sc = 0.08838834764831843f;  // 1/sqrt(128)

  // ---- Pass 1: logits, 2 chunks of 4 keys (8 LDG.128 front-batched each) --
#pragma unroll
  for (int g = 0; g < 2; g++) {
    float4 kA[4], kB[4];
#pragma unroll
    for (int i = 0; i < 4; i++) kA[i] = s4[t + (g * 4 + i) * 256];
#pragma unroll
    for (int i = 0; i < 4; i++) kB[i] = st4[t + (g * 4 + i) * 256];
#pragma unroll
    for (int i = 0; i < 4; i++) {
      float s0 = kA[i].x * qA0.x + kA[i].y * qA0.y + kA[i].z * qA0.z + kA[i].w * qA0.w +
                 kB[i].x * qB0.x + kB[i].y * qB0.y + kB[i].z * qB0.z + kB[i].w * qB0.w;
      float s1 = kA[i].x * qA1.x + kA[i].y * qA1.y + kA[i].z * qA1.z + kA[i].w * qA1.w +
                 kB[i].x * qB1.x + kB[i].y * qB1.y + kB[i].z * qB1.z + kB[i].w * qB1.w;
#pragma unroll
      for (int o = 16; o; o >>= 1) {
        s0 += __shfl_xor_sync(0xffffffffu, s0, o);
        s1 += __shfl_xor_sync(0xffffffffu, s1, o);
      }
      if (l == 0) {
        int n = w + 8 * (g * 4 + i);
        int masked = (mflag[n] != 0.f);
        aw[n] = masked ? -1e10f : s0 * sc;
        aw[64 + n] = masked ? -1e10f : s1 * sc;
      }
    }
  }
  __syncthreads();

  // ---- Softmax (warp 0: head 0, warp 1: head 1) ----
  if (w < 2) {
    float x0 = aw[w * 64 + l], x1 = aw[w * 64 + 32 + l];
    float m = fmaxf(x0, x1);
#pragma unroll
    for (int o = 16; o; o >>= 1) m = fmaxf(m, __shfl_xor_sync(0xffffffffu, m, o));
    float e0 = __expf(x0 - m), e1 = __expf(x1 - m);
    float s = e0 + e1;
#pragma unroll
    for (int o = 16; o; o >>= 1) s += __shfl_xor_sync(0xffffffffu, s, o);
    float inv = 1.f / s;
    float a0 = e0 * inv, a1 = e1 * inv;
    aw[w * 64 + l] = a0;
    aw[w * 64 + 32 + l] = a1;
    out[524288 + (w * 4096 + b) * 64 + l] = a0;
    out[524288 + (w * 4096 + b) * 64 + 32 + l] = a1;
  }
  __syncthreads();

  // ---- Pass 2: weighted key sums, keys re-read (L2-hot) ----
  float4 aA0 = {0,0,0,0}, aB0 = {0,0,0,0}, aA1 = {0,0,0,0}, aB1 = {0,0,0,0};
#pragma unroll
  for (int g = 0; g < 2; g++) {
    float4 kA[4], kB[4];
#pragma unroll
    for (int i = 0; i < 4; i++) kA[i] = s4[t + (g * 4 + i) * 256];
#pragma unroll
    for (int i = 0; i < 4; i++) kB[i] = st4[t + (g * 4 + i) * 256];
#pragma unroll
    for (int i = 0; i < 4; i++) {
      int n = w + 8 * (g * 4 + i);
      float a0 = aw[n], a1 = aw[64 + n];
      aA0.x += a0 * kA[i].x; aA0.y += a0 * kA[i].y; aA0.z += a0 * kA[i].z; aA0.w += a0 * kA[i].w;
      aB0.x += a0 * kB[i].x; aB0.y += a0 * kB[i].y; aB0.z += a0 * kB[i].z; aB0.w += a0 * kB[i].w;
      aA1.x += a1 * kA[i].x; aA1.y += a1 * kA[i].y; aA1.z += a1 * kA[i].z; aA1.w += a1 * kA[i].w;
      aB1.x += a1 * kB[i].x; aB1.y += a1 * kB[i].y; aB1.z += a1 * kB[i].z; aB1.w += a1 * kB[i].w;
    }
  }
  *(float4*)&red[w * 512 + 4 * l] = aA0;
  *(float4*)&red[w * 512 + 128 + 4 * l] = aB0;
  *(float4*)&red[w * 512 + 256 + 4 * l] = aA1;
  *(float4*)&red[w * 512 + 384 + 4 * l] = aB1;
  __syncthreads();

  float kb0 = 0.f, kb1 = 0.f;
#pragma unroll
  for (int j = 0; j < 8; j++) {
    kb0 += red[j * 512 + t];
    kb1 += red[j * 512 + 256 + t];
  }
  g_kbar[b * 512 + t] = kb0;
  g_kbar[b * 512 + 256 + t] = kb1;
}

// ---------------------------------------------------------------------------
// K3a: g_x = kbar(4096x512) @ P(512x256) + fc_b + q_in.
// ---------------------------------------------------------------------------
__global__ __launch_bounds__(256) void k3a_fc(const float* __restrict__ src,
                                              const float* __restrict__ srct,
                                              const float* __restrict__ fc_b) {
  __shared__ float As[32][64];
  __shared__ float Bs[32][64];
  int bm = blockIdx.x * 64, bn = blockIdx.y * 64;
  int t = threadIdx.x;
  int ty = t >> 4, tx = t & 15;
  ull acc[4][2];
#pragma unroll
  for (int i = 0; i < 4; i++) { acc[i][0] = 0ull; acc[i][1] = 0ull; }

  float4 pa[2], pb[2];
  auto loadA = [&](int kt) {
#pragma unroll
    for (int i = 0; i < 2; i++) {
      int e = t + i * 256, r = e >> 3, g = e & 7;
      pa[i] = *(const float4*)&g_kbar[(bm + r) * 512 + kt * 32 + g * 4];
    }
  };
  auto loadB = [&](int kt) {
#pragma unroll
    for (int i = 0; i < 2; i++) {
      int e = t + i * 256, kk = e >> 4, n4 = e & 15;
      pb[i] = *(const float4*)&g_P[(kt * 32 + kk) * 256 + bn + n4 * 4];
    }
  };
  loadA(0); loadB(0);
  for (int kt = 0; kt < 16; kt++) {
#pragma unroll
    for (int i = 0; i < 2; i++) {
      int e = t + i * 256, r = e >> 3, g = e & 7;
      As[g * 4 + 0][r] = pa[i].x; As[g * 4 + 1][r] = pa[i].y;
      As[g * 4 + 2][r] = pa[i].z; As[g * 4 + 3][r] = pa[i].w;
    }
#pragma unroll
    for (int i = 0; i < 2; i++) {
      int e = t + i * 256, kk = e >> 4, n4 = e & 15;
      *(float4*)&Bs[kk][n4 * 4] = pb[i];
    }
    __syncthreads();
    if (kt < 15) { loadA(kt + 1); loadB(kt + 1); }
#pragma unroll
    for (int kk = 0; kk < 32; kk++) {
      float4 a0 = *(const float4*)&As[kk][ty * 4];
      ull A[4] = {pk2(a0.x), pk2(a0.y), pk2(a0.z), pk2(a0.w)};
      ull b0 = *(const ull*)&Bs[kk][tx * 4];
      ull b1 = *(const ull*)&Bs[kk][tx * 4 + 2];
#pragma unroll
      for (int i = 0; i < 4; i++) { fma2(acc[i][0], A[i], b0); fma2(acc[i][1], A[i], b1); }
    }
    __syncthreads();
  }
#pragma unroll
  for (int i = 0; i < 4; i++) {
    int r = bm + ty * 4 + i;
    float2 p0 = upk(acc[i][0]), p1 = upk(acc[i][1]);
    float o[4] = {p0.x, p0.y, p1.x, p1.y};
    float4 v;
    float* vp = &v.x;
#pragma unroll
    for (int j = 0; j < 4; j++) {
      int c = bn + tx * 4 + j;
      float resid = (c < 128) ? src[r * 128 + c] : srct[r * 128 + c - 128];
      vp[j] = o[j] + fc_b[c] + resid;
    }
    *(float4*)&g_x[r * 256 + bn + tx * 4] = v;
  }
}

// ---------------------------------------------------------------------------
// K3b: per 16-batch tile: LN(g_x) -> xh, src append, GEMM2 relu, GEMM3 -> out.
// ---------------------------------------------------------------------------
__global__ __launch_bounds__(256) void k3b_ffn(
    const float* __restrict__ src, const float* __restrict__ ln_g,
    const float* __restrict__ ln_b, const float* __restrict__ fc1_w,
    const float* __restrict__ fc1_b, const float* __restrict__ fc2_w,
    const float* __restrict__ fc2_b, float* __restrict__ out) {
  extern __shared__ float sm3[];
  float* xh = sm3;           // 16 x 388 (padded)
  float* Bs = xh + 16 * 388; // 32 x 128
  float* hm = Bs + 4096;     // 16 x 132 (padded)
  int bb = blockIdx.x * 16;
  int t = threadIdx.x;
  int w = t >> 5, l = t & 31;

#pragma unroll
  for (int i = 0; i < 4; i++) {
    int e = t + i * 256, r = e >> 6, c4 = e & 63;
    *(float4*)&xh[r * 388 + c4 * 4] = *(const float4*)&g_x[(bb + r) * 256 + c4 * 4];
  }
#pragma unroll
  for (int i = 0; i < 2; i++) {
    int e = t + i * 256, r = e >> 5, c4 = e & 31;
    *(float4*)&xh[r * 388 + 256 + c4 * 4] = *(const float4*)&src[(bb + r) * 128 + c4 * 4];
  }
  __syncthreads();

#pragma unroll
  for (int rr = 0; rr < 2; rr++) {
    int r = w * 2 + rr;
    float s1 = 0.f, s2 = 0.f;
#pragma unroll
    for (int q = 0; q < 8; q++) {
      float x = xh[r * 388 + l + 32 * q];
      s1 += x; s2 += x * x;
    }
#pragma unroll
    for (int o = 16; o; o >>= 1) {
      s1 += __shfl_xor_sync(0xffffffffu, s1, o);
      s2 += __shfl_xor_sync(0xffffffffu, s2, o);
    }
    float mu = s1 * (1.f / 256.f);
    float var = s2 * (1.f / 256.f) - mu * mu;
    float rs = rsqrtf(var + 1e-5f);
#pragma unroll
    for (int q = 0; q < 8; q++) {
      int c = l + 32 * q;
      float x = xh[r * 388 + c];
      xh[r * 388 + c] = (x - mu) * rs * ln_g[c] + ln_b[c];
    }
  }
  __syncthreads();

  int ty2 = w, tx2 = l;
  {
    ull acc[2][2];
    acc[0][0] = acc[0][1] = acc[1][0] = acc[1][1] = 0ull;
    float4 pb[4];
    auto loadB = [&](int kt) {
#pragma unroll
      for (int i = 0; i < 4; i++) {
        int e = t + i * 256, kk = e >> 5, c4 = e & 31;
        pb[i] = *(const float4*)&fc1_w[(kt * 32 + kk) * 128 + c4 * 4];
      }
    };
    loadB(0);
    for (int kt = 0; kt < 12; kt++) {
#pragma unroll
      for (int i = 0; i < 4; i++) {
        int e = t + i * 256, kk = e >> 5, c4 = e & 31;
        *(float4*)&Bs[kk * 128 + c4 * 4] = pb[i];
      }
      __syncthreads();
      if (kt < 11) loadB(kt + 1);
#pragma unroll
      for (int kk = 0; kk < 32; kk++) {
        int k = kt * 32 + kk;
        ull A0 = pk2(xh[(ty2 * 2 + 0) * 388 + k]);
        ull A1 = pk2(xh[(ty2 * 2 + 1) * 388 + k]);
        ull b0 = *(const ull*)&Bs[kk * 128 + tx2 * 4];
        ull b1 = *(const ull*)&Bs[kk * 128 + tx2 * 4 + 2];
        fma2(acc[0][0], A0, b0); fma2(acc[0][1], A0, b1);
        fma2(acc[1][0], A1, b0); fma2(acc[1][1], A1, b1);
      }
      __syncthreads();
    }
#pragma unroll
    for (int i = 0; i < 2; i++) {
      float2 p0 = upk(acc[i][0]), p1 = upk(acc[i][1]);
      int r = ty2 * 2 + i, c = tx2 * 4;
      hm[r * 132 + c + 0] = fmaxf(p0.x + fc1_b[c + 0], 0.f);
      hm[r * 132 + c + 1] = fmaxf(p0.y + fc1_b[c + 1], 0.f);
      hm[r * 132 + c + 2] = fmaxf(p1.x + fc1_b[c + 2], 0.f);
      hm[r * 132 + c + 3] = fmaxf(p1.y + fc1_b[c + 3], 0.f);
    }
  }
  __syncthreads();

  {
    ull acc[2][2];
    acc[0][0] = acc[0][1] = acc[1][0] = acc[1][1] = 0ull;
    float4 pb[4];
    auto loadB = [&](int kt) {
#pragma unroll
      for (int i = 0; i < 4; i++) {
        int e = t + i * 256, kk = e >> 5, c4 = e & 31;
        pb[i] = *(const float4*)&fc2_w[(kt * 32 + kk) * 128 + c4 * 4];
      }
    };
    loadB(0);
    for (int kt = 0; kt < 4; kt++) {
#pragma unroll
      for (int i = 0; i < 4; i++) {
        int e = t + i * 256, kk = e >> 5, c4 = e & 31;
        *(float4*)&Bs[kk * 128 + c4 * 4] = pb[i];
      }
      __syncthreads();
      if (kt < 3) loadB(kt + 1);
#pragma unroll
      for (int kk = 0; kk < 32; kk++) {
        int k = kt * 32 + kk;
        ull A0 = pk2(hm[(ty2 * 2 + 0) * 132 + k]);
        ull A1 = pk2(hm[(ty2 * 2 + 1) * 132 + k]);
        ull b0 = *(const ull*)&Bs[kk * 128 + tx2 * 4];
        ull b1 = *(const ull*)&Bs[kk * 128 + tx2 * 4 + 2];
        fma2(acc[0][0], A0, b0); fma2(acc[0][1], A0, b1);
        fma2(acc[1][0], A1, b0); fma2(acc[1][1], A1, b1);
      }
      __syncthreads();
    }
#pragma unroll
    for (int i = 0; i < 2; i++) {
      float2 p0 = upk(acc[i][0]), p1 = upk(acc[i][1]);
      int r = bb + ty2 * 2 + i, c = tx2 * 4;
      float4 v = make_float4(p0.x + fc2_b[c], p0.y + fc2_b[c + 1],
                             p1.x + fc2_b[c + 2], p1.y + fc2_b[c + 3]);
      *(float4*)&out[r * 128 + c] = v;
    }
  }
}

// ---------------------------------------------------------------------------
extern "C" void kernel_launch(void* const* d_in, const int* in_sizes, int n_in,
                              void* d_out, int out_size) {
  const float* src   = (const float*)d_in[0];
  const float* src_t = (const float*)d_in[1];
  const float* seq   = (const float*)d_in[2];
  const float* seq_t = (const float*)d_in[3];
  const void*  mask  = d_in[4];
  const float* w_qs  = (const float*)d_in[5];
  const float* w_ks  = (const float*)d_in[6];
  const float* w_vs  = (const float*)d_in[7];
  const float* fc_w  = (const float*)d_in[8];
  const float* fc_b  = (const float*)d_in[9];
  const float* ln_g  = (const float*)d_in[10];
  const float* ln_b  = (const float*)d_in[11];
  const float* fc1_w = (const float*)d_in[12];
  const float* fc1_b = (const float*)d_in[13];
  const float* fc2_w = (const float*)d_in[14];
  const float* fc2_b = (const float*)d_in[15];
  float* out = (float*)d_out;

  const int K0_SMEM = (64 * 132 * 2) * 4;                 // 67584 B
  const int K3B_SMEM = (16 * 388 + 4096 + 16 * 132) * 4;  // 49664 B
  cudaFuncSetAttribute(k0_precompute, cudaFuncAttributeMaxDynamicSharedMemorySize, K0_SMEM);
  cudaFuncSetAttribute(k3b_ffn, cudaFuncAttributeMaxDynamicSharedMemorySize, K3B_SMEM);

  k0_precompute<<<64, 256, K0_SMEM>>>(w_qs, w_ks, w_vs, fc_w);
  k1_qk<<<dim3(64, 4), 256>>>(src, src_t);
  k2_attn<<<4096, 256>>>(seq, seq_t, mask, out);
  k3a_fc<<<dim3(64, 4), 256>>>(src, src_t, fc_b);
  k3b_ffn<<<256, 256, K3B_SMEM>>>(src, ln_g, ln_b, fc1_w, fc1_b, fc2_w, fc2_b,
                                  out);
}